// round 1
// baseline (speedup 1.0000x reference)
#include <cuda_runtime.h>
#include <math.h>

#define T_SEQ 2048
#define C_DIM 1024
#define C3    3072
#define NH    16
#define HD    64
#define M_ROWS 4096   // B*T

// Scratch (static device arrays — allocation-guard safe)
__device__ float g_qkv[(size_t)M_ROWS * C3];   // (B*T, 3C)
__device__ float g_y[(size_t)M_ROWS * C_DIM];  // (B*T, C) attention output

// ---------------------------------------------------------------------------
// SGEMM (NT): C[m][n] = sum_k A[m][k] * B[n][k]
// A: M x K row-major, B: N x K row-major, C: M x N row-major
// 128x128 block tile, K-tile 8, 256 threads, 8x8 per-thread micro-tile.
// ---------------------------------------------------------------------------
__global__ __launch_bounds__(256) void sgemm_nt(const float* __restrict__ A,
                                                const float* __restrict__ B,
                                                float* __restrict__ C,
                                                int M, int N, int K) {
    __shared__ float As[8][132];
    __shared__ float Bs[8][132];
    const int tid = threadIdx.x;
    const int tx = tid & 15, ty = tid >> 4;
    const int row0 = blockIdx.y * 128;
    const int col0 = blockIdx.x * 128;
    const int lrow = tid >> 1;
    const int lk = (tid & 1) * 4;

    const float* Ap = A + (size_t)(row0 + lrow) * K + lk;
    const float* Bp = B + (size_t)(col0 + lrow) * K + lk;

    float acc[8][8];
#pragma unroll
    for (int i = 0; i < 8; i++)
#pragma unroll
        for (int j = 0; j < 8; j++) acc[i][j] = 0.f;

    for (int k0 = 0; k0 < K; k0 += 8) {
        float4 av = *(const float4*)(Ap + k0);
        float4 bv = *(const float4*)(Bp + k0);
        __syncthreads();
        As[lk + 0][lrow] = av.x; As[lk + 1][lrow] = av.y;
        As[lk + 2][lrow] = av.z; As[lk + 3][lrow] = av.w;
        Bs[lk + 0][lrow] = bv.x; Bs[lk + 1][lrow] = bv.y;
        Bs[lk + 2][lrow] = bv.z; Bs[lk + 3][lrow] = bv.w;
        __syncthreads();
#pragma unroll
        for (int kk = 0; kk < 8; kk++) {
            float a[8], b[8];
            *(float4*)&a[0] = *(const float4*)&As[kk][ty * 8];
            *(float4*)&a[4] = *(const float4*)&As[kk][ty * 8 + 4];
            *(float4*)&b[0] = *(const float4*)&Bs[kk][tx * 8];
            *(float4*)&b[4] = *(const float4*)&Bs[kk][tx * 8 + 4];
#pragma unroll
            for (int i = 0; i < 8; i++)
#pragma unroll
                for (int j = 0; j < 8; j++)
                    acc[i][j] += a[i] * b[j];
        }
    }
#pragma unroll
    for (int i = 0; i < 8; i++) {
        float* cp = C + (size_t)(row0 + ty * 8 + i) * N + col0 + tx * 8;
        *(float4*)cp = make_float4(acc[i][0], acc[i][1], acc[i][2], acc[i][3]);
        *(float4*)(cp + 4) = make_float4(acc[i][4], acc[i][5], acc[i][6], acc[i][7]);
    }
}

// ---------------------------------------------------------------------------
// RoPE: applied in place to q (cols [0,C)) and k (cols [C,2C)) of g_qkv.
// Interleaved pairs, position = t (row % T), freq index = (col % HD) / 2.
// One thread per pair; 4096 rows * 1024 pairs = 4,194,304 threads exactly.
// ---------------------------------------------------------------------------
__global__ __launch_bounds__(256) void rope_kernel(float* __restrict__ qkv) {
    int idx = blockIdx.x * blockDim.x + threadIdx.x;
    int row = idx >> 10;        // /1024 pairs per row
    int p   = idx & 1023;
    int col = p * 2;            // within [0, 2C)
    int t   = row & (T_SEQ - 1);
    int dd  = col & (HD - 1);   // even, 0..62
    // theta = 10000^(-dd/64); -ln(10000)/64 = -0.14391156831212787
    float theta = (float)exp((double)dd * -0.14391156831212787);
    float ang = (float)t * theta;
    float sn, cs;
    sincosf(ang, &sn, &cs);
    float2* ptr = (float2*)(qkv + (size_t)row * C3 + col);
    float2 v = *ptr;
    float o0 = v.x * cs - v.y * sn;
    float o1 = v.y * cs + v.x * sn;
    *ptr = make_float2(o0, o1);
}

// ---------------------------------------------------------------------------
// Flash attention (fp32): 64x64 Q/K tiles, online softmax, causal tile skip.
// grid = (T/64, B*H), 256 threads = 16x16, each thread 4x4 of S and 4x4 of O.
// qkv layout per row: [q(1024) | k(1024) | v(1024)], head h at offset h*64.
// ---------------------------------------------------------------------------
__global__ __launch_bounds__(256) void flash_kernel(const float* __restrict__ qkv,
                                                    float* __restrict__ y) {
    extern __shared__ float sm[];
    float* Qs = sm;                 // [64][68]  (transposed: [d][row])
    float* Ks = sm + 64 * 68;       // [64][68]  (transposed: [d][col])
    float* Vs = sm + 2 * 64 * 68;   // [64][68]  (row-major: [kj][d])
    float* Ps = sm + 3 * 64 * 68;   // [64][64]

    const int tid = threadIdx.x;
    const int tx = tid & 15, ty = tid >> 4;
    const int qt = blockIdx.x;
    const int b  = blockIdx.y >> 4;
    const int h  = blockIdx.y & 15;
    const int q0 = qt * 64;

    const float* qb = qkv + (size_t)b * T_SEQ * C3 + h * HD;
    const float* kb = qb + C_DIM;
    const float* vb = qb + 2 * C_DIM;

    // Load Q tile (pre-scaled by 1/sqrt(D)), transposed [d][row]
#pragma unroll
    for (int r = 0; r < 4; r++) {
        int fi = tid + r * 256;       // 0..1023 float4s
        int qi = fi >> 4;
        int d4 = (fi & 15) * 4;
        float4 v = *(const float4*)(qb + (size_t)(q0 + qi) * C3 + d4);
        Qs[(d4 + 0) * 68 + qi] = v.x * 0.125f;
        Qs[(d4 + 1) * 68 + qi] = v.y * 0.125f;
        Qs[(d4 + 2) * 68 + qi] = v.z * 0.125f;
        Qs[(d4 + 3) * 68 + qi] = v.w * 0.125f;
    }

    float o[4][4];
    float m[4], l[4];
#pragma unroll
    for (int i = 0; i < 4; i++) {
        m[i] = -3.0e38f;
        l[i] = 0.f;
#pragma unroll
        for (int j = 0; j < 4; j++) o[i][j] = 0.f;
    }

    for (int kt = 0; kt <= qt; kt++) {
        const int k0 = kt * 64;
        __syncthreads();   // prior-iteration smem reads complete
#pragma unroll
        for (int r = 0; r < 4; r++) {
            int fi = tid + r * 256;
            int ki = fi >> 4;
            int d4 = (fi & 15) * 4;
            float4 kv = *(const float4*)(kb + (size_t)(k0 + ki) * C3 + d4);
            Ks[(d4 + 0) * 68 + ki] = kv.x; Ks[(d4 + 1) * 68 + ki] = kv.y;
            Ks[(d4 + 2) * 68 + ki] = kv.z; Ks[(d4 + 3) * 68 + ki] = kv.w;
            float4 vv = *(const float4*)(vb + (size_t)(k0 + ki) * C3 + d4);
            *(float4*)&Vs[ki * 68 + d4] = vv;
        }
        __syncthreads();

        // S = Q K^T (4x4 per thread)
        float s[4][4];
#pragma unroll
        for (int i = 0; i < 4; i++)
#pragma unroll
            for (int j = 0; j < 4; j++) s[i][j] = 0.f;
#pragma unroll 8
        for (int d = 0; d < 64; d++) {
            float4 qa = *(const float4*)&Qs[d * 68 + ty * 4];
            float4 ka = *(const float4*)&Ks[d * 68 + tx * 4];
            float aq[4] = {qa.x, qa.y, qa.z, qa.w};
            float ak[4] = {ka.x, ka.y, ka.z, ka.w};
#pragma unroll
            for (int i = 0; i < 4; i++)
#pragma unroll
                for (int j = 0; j < 4; j++)
                    s[i][j] += aq[i] * ak[j];
        }

        // Causal mask (diagonal tile only; earlier tiles fully valid)
        if (kt == qt) {
#pragma unroll
            for (int i = 0; i < 4; i++)
#pragma unroll
                for (int j = 0; j < 4; j++)
                    if (tx * 4 + j > ty * 4 + i) s[i][j] = -3.0e38f;
        }

        // Online softmax (row reductions across tx via shuffles within 16-lane groups)
#pragma unroll
        for (int i = 0; i < 4; i++) {
            float mx = fmaxf(fmaxf(s[i][0], s[i][1]), fmaxf(s[i][2], s[i][3]));
#pragma unroll
            for (int off = 8; off; off >>= 1)
                mx = fmaxf(mx, __shfl_xor_sync(0xffffffffu, mx, off));
            float mn = fmaxf(m[i], mx);
            float corr = __expf(m[i] - mn);
            float rs = 0.f;
#pragma unroll
            for (int j = 0; j < 4; j++) {
                float p = __expf(s[i][j] - mn);
                s[i][j] = p;
                rs += p;
            }
#pragma unroll
            for (int off = 8; off; off >>= 1)
                rs += __shfl_xor_sync(0xffffffffu, rs, off);
            l[i] = l[i] * corr + rs;
            m[i] = mn;
#pragma unroll
            for (int j = 0; j < 4; j++) o[i][j] *= corr;
#pragma unroll
            for (int j = 0; j < 4; j++)
                Ps[(ty * 4 + i) * 64 + tx * 4 + j] = s[i][j];
        }
        __syncthreads();

        // O += P @ V  (thread owns rows ty*4+i, d-cols tx*4+j)
#pragma unroll 4
        for (int kj = 0; kj < 64; kj++) {
            float4 v = *(const float4*)&Vs[kj * 68 + tx * 4];
#pragma unroll
            for (int i = 0; i < 4; i++) {
                float p = Ps[(ty * 4 + i) * 64 + kj];
                o[i][0] += p * v.x; o[i][1] += p * v.y;
                o[i][2] += p * v.z; o[i][3] += p * v.w;
            }
        }
    }

    // Epilogue: normalize and write y (b, t, h, d) -> (B*T, C)
#pragma unroll
    for (int i = 0; i < 4; i++) {
        float inv = 1.0f / l[i];
        float4 st = make_float4(o[i][0] * inv, o[i][1] * inv,
                                o[i][2] * inv, o[i][3] * inv);
        *(float4*)(y + (size_t)(b * T_SEQ + q0 + ty * 4 + i) * C_DIM + h * HD + tx * 4) = st;
    }
}

// ---------------------------------------------------------------------------
extern "C" void kernel_launch(void* const* d_in, const int* in_sizes, int n_in,
                              void* d_out, int out_size) {
    const float* x      = (const float*)d_in[0];
    const float* w_qkv  = (const float*)d_in[1];
    const float* w_proj = (const float*)d_in[2];
    float* out = (float*)d_out;

    float *qkv, *y;
    cudaGetSymbolAddress((void**)&qkv, g_qkv);
    cudaGetSymbolAddress((void**)&y, g_y);

    // 1) QKV projection: (4096,3072) = x(4096,1024) @ w_qkv^T
    sgemm_nt<<<dim3(3072 / 128, 4096 / 128), 256>>>(x, w_qkv, qkv, 4096, 3072, 1024);

    // 2) RoPE on q,k in place
    rope_kernel<<<(M_ROWS * 1024) / 256, 256>>>(qkv);

    // 3) Causal flash attention
    const int smem_bytes = (3 * 64 * 68 + 64 * 64) * 4;  // 68608
    cudaFuncSetAttribute(flash_kernel, cudaFuncAttributeMaxDynamicSharedMemorySize, smem_bytes);
    flash_kernel<<<dim3(T_SEQ / 64, 2 * NH), 256, smem_bytes>>>(qkv, y);

    // 4) Output projection: (4096,1024) = y @ w_proj^T
    sgemm_nt<<<dim3(1024 / 128, 4096 / 128), 256>>>(y, w_proj, out, 4096, 1024, 1024);
}

// round 5
// speedup vs baseline: 1.5032x; 1.5032x over previous
#include <cuda_runtime.h>
#include <cuda_bf16.h>
#include <math.h>
#include <cstdint>

#define T_SEQ 2048
#define C_DIM 1024
#define C3    3072
#define NH    16
#define HD    64
#define M_ROWS 4096   // B*T

// Scratch (static device arrays — allocation-guard safe)
__device__ float g_qkv[(size_t)M_ROWS * C3];   // (B*T, 3C)
__device__ float g_y[(size_t)M_ROWS * C_DIM];  // attention output

__device__ __forceinline__ uint32_t smem_u32(const void* p) {
    uint32_t a;
    asm("{ .reg .u64 t; cvta.to.shared.u64 t, %1; cvt.u32.u64 %0, t; }"
        : "=r"(a) : "l"(p));
    return a;
}

// ---------------------------------------------------------------------------
// Tensor-core GEMM (NT): C[m][n] = sum_k A[m][k] * B[n][k], fp32 in/out.
// bf16 3-product split (hi*hi + lo*hi + hi*lo) with fp32 accumulation.
// Block 128x128, 8 warps (2x4), warp tile 64x32, K-tile 32.
// ---------------------------------------------------------------------------
#define ASTRIDE 40   // bf16 elements per smem row (32 data + 8 pad); 80B = 5*16B

__device__ __forceinline__ void mma_bf16(float* c, const uint32_t* a, const uint32_t* b) {
    asm volatile(
        "mma.sync.aligned.m16n8k16.row.col.f32.bf16.bf16.f32 "
        "{%0,%1,%2,%3}, {%4,%5,%6,%7}, {%8,%9}, {%0,%1,%2,%3};"
        : "+f"(c[0]), "+f"(c[1]), "+f"(c[2]), "+f"(c[3])
        : "r"(a[0]), "r"(a[1]), "r"(a[2]), "r"(a[3]), "r"(b[0]), "r"(b[1]));
}
__device__ __forceinline__ void ldmx4(uint32_t* r, uint32_t addr) {
    asm volatile("ldmatrix.sync.aligned.m8n8.x4.shared.b16 {%0,%1,%2,%3}, [%4];"
        : "=r"(r[0]), "=r"(r[1]), "=r"(r[2]), "=r"(r[3]) : "r"(addr));
}
__device__ __forceinline__ void ldmx2(uint32_t* r, uint32_t addr) {
    asm volatile("ldmatrix.sync.aligned.m8n8.x2.shared.b16 {%0,%1}, [%2];"
        : "=r"(r[0]), "=r"(r[1]) : "r"(addr));
}

__global__ __launch_bounds__(256, 2) void gemm_mma(const float* __restrict__ A,
                                                   const float* __restrict__ B,
                                                   float* __restrict__ C,
                                                   int M, int N, int K) {
    // [0]=hi, [1]=lo planes
    __shared__ __align__(16) __nv_bfloat16 sA[2][128 * ASTRIDE];
    __shared__ __align__(16) __nv_bfloat16 sB[2][128 * ASTRIDE];

    const int tid = threadIdx.x;
    const int wid = tid >> 5, lane = tid & 31;
    const int wm = wid >> 2, wn = wid & 3;     // warp grid 2 x 4
    const int m0 = blockIdx.y * 128;
    const int n0 = blockIdx.x * 128;

    float acc[4][4][4];
#pragma unroll
    for (int i = 0; i < 4; i++)
#pragma unroll
        for (int j = 0; j < 4; j++)
#pragma unroll
            for (int r = 0; r < 4; r++) acc[i][j][r] = 0.f;

    // ldmatrix per-thread base addresses (bytes)
    // A x4: lanes 0-15 -> rows (lane%16), lanes 16-31 -> k+8 halves
    const uint32_t saddr0 = smem_u32(&sA[0][0]);
    const uint32_t sbddr0 = smem_u32(&sB[0][0]);
    const uint32_t a_base = saddr0 + ((wm * 64 + (lane & 15)) * ASTRIDE) * 2 + (lane >> 4) * 16;
    const uint32_t b_base = sbddr0 + ((wn * 32 + (lane & 7)) * ASTRIDE) * 2 + ((lane >> 3) & 1) * 16;
    const uint32_t PLANE = 128 * ASTRIDE * 2;  // bytes between hi and lo planes

    // loader indices: 4 float4 per thread per tile (128 rows x 8 float4)
    const float* pA = A + (size_t)m0 * K;
    const float* pB = B + (size_t)n0 * K;

    for (int kt = 0; kt < K; kt += 32) {
        __syncthreads();
#pragma unroll
        for (int r = 0; r < 4; r++) {
            int idx = tid + 256 * r;
            int row = idx >> 3;
            int c4 = (idx & 7) << 2;
            // A
            float4 v = *(const float4*)(pA + (size_t)row * K + kt + c4);
            __nv_bfloat162 h0 = __floats2bfloat162_rn(v.x, v.y);
            __nv_bfloat162 h1 = __floats2bfloat162_rn(v.z, v.w);
            float2 f0 = __bfloat1622float2(h0);
            float2 f1 = __bfloat1622float2(h1);
            __nv_bfloat162 l0 = __floats2bfloat162_rn(v.x - f0.x, v.y - f0.y);
            __nv_bfloat162 l1 = __floats2bfloat162_rn(v.z - f1.x, v.w - f1.y);
            *(__nv_bfloat162*)&sA[0][row * ASTRIDE + c4] = h0;
            *(__nv_bfloat162*)&sA[0][row * ASTRIDE + c4 + 2] = h1;
            *(__nv_bfloat162*)&sA[1][row * ASTRIDE + c4] = l0;
            *(__nv_bfloat162*)&sA[1][row * ASTRIDE + c4 + 2] = l1;
            // B
            v = *(const float4*)(pB + (size_t)row * K + kt + c4);
            h0 = __floats2bfloat162_rn(v.x, v.y);
            h1 = __floats2bfloat162_rn(v.z, v.w);
            f0 = __bfloat1622float2(h0);
            f1 = __bfloat1622float2(h1);
            l0 = __floats2bfloat162_rn(v.x - f0.x, v.y - f0.y);
            l1 = __floats2bfloat162_rn(v.z - f1.x, v.w - f1.y);
            *(__nv_bfloat162*)&sB[0][row * ASTRIDE + c4] = h0;
            *(__nv_bfloat162*)&sB[0][row * ASTRIDE + c4 + 2] = h1;
            *(__nv_bfloat162*)&sB[1][row * ASTRIDE + c4] = l0;
            *(__nv_bfloat162*)&sB[1][row * ASTRIDE + c4 + 2] = l1;
        }
        __syncthreads();

#pragma unroll
        for (int ks = 0; ks < 2; ks++) {
            uint32_t bhi[4][2], blo[4][2];
#pragma unroll
            for (int nt = 0; nt < 4; nt++) {
                uint32_t ba = b_base + nt * (8 * ASTRIDE * 2) + ks * 32;
                ldmx2(bhi[nt], ba);
                ldmx2(blo[nt], ba + PLANE);
            }
#pragma unroll
            for (int mt = 0; mt < 4; mt++) {
                uint32_t ahi[4], alo[4];
                uint32_t aa = a_base + mt * (16 * ASTRIDE * 2) + ks * 32;
                ldmx4(ahi, aa);
                ldmx4(alo, aa + PLANE);
#pragma unroll
                for (int nt = 0; nt < 4; nt++) {
                    mma_bf16(acc[mt][nt], ahi, bhi[nt]);
                    mma_bf16(acc[mt][nt], alo, bhi[nt]);
                    mma_bf16(acc[mt][nt], ahi, blo[nt]);
                }
            }
        }
    }

    // Epilogue
#pragma unroll
    for (int mt = 0; mt < 4; mt++) {
#pragma unroll
        for (int nt = 0; nt < 4; nt++) {
            int gm = m0 + wm * 64 + mt * 16 + (lane >> 2);
            int gn = n0 + wn * 32 + nt * 8 + (lane & 3) * 2;
            *(float2*)&C[(size_t)gm * N + gn] = make_float2(acc[mt][nt][0], acc[mt][nt][1]);
            *(float2*)&C[(size_t)(gm + 8) * N + gn] = make_float2(acc[mt][nt][2], acc[mt][nt][3]);
        }
    }
}

// ---------------------------------------------------------------------------
// RoPE: in place on q (cols [0,C)) and k (cols [C,2C)) of g_qkv.
// ---------------------------------------------------------------------------
__global__ __launch_bounds__(256) void rope_kernel(float* __restrict__ qkv) {
    int idx = blockIdx.x * blockDim.x + threadIdx.x;
    int row = idx >> 10;
    int p   = idx & 1023;
    int col = p * 2;
    int t   = row & (T_SEQ - 1);
    int dd  = col & (HD - 1);
    float theta = (float)exp((double)dd * -0.14391156831212787);
    float ang = (float)t * theta;
    float sn, cs;
    sincosf(ang, &sn, &cs);
    float2* ptr = (float2*)(qkv + (size_t)row * C3 + col);
    float2 v = *ptr;
    *ptr = make_float2(v.x * cs - v.y * sn, v.y * cs + v.x * sn);
}

// ---------------------------------------------------------------------------
// Flash attention (fp32): 64x64 tiles, online softmax, causal tile skip.
// ---------------------------------------------------------------------------
__global__ __launch_bounds__(256) void flash_kernel(const float* __restrict__ qkv,
                                                    float* __restrict__ y) {
    extern __shared__ float smf[];
    float* Qs = smf;
    float* Ks = smf + 64 * 68;
    float* Vs = smf + 2 * 64 * 68;
    float* Ps = smf + 3 * 64 * 68;

    const int tid = threadIdx.x;
    const int tx = tid & 15, ty = tid >> 4;
    const int qt = blockIdx.x;
    const int b  = blockIdx.y >> 4;
    const int h  = blockIdx.y & 15;
    const int q0 = qt * 64;

    const float* qb = qkv + (size_t)b * T_SEQ * C3 + h * HD;
    const float* kb = qb + C_DIM;
    const float* vb = qb + 2 * C_DIM;

#pragma unroll
    for (int r = 0; r < 4; r++) {
        int fi = tid + r * 256;
        int qi = fi >> 4;
        int d4 = (fi & 15) * 4;
        float4 v = *(const float4*)(qb + (size_t)(q0 + qi) * C3 + d4);
        Qs[(d4 + 0) * 68 + qi] = v.x * 0.125f;
        Qs[(d4 + 1) * 68 + qi] = v.y * 0.125f;
        Qs[(d4 + 2) * 68 + qi] = v.z * 0.125f;
        Qs[(d4 + 3) * 68 + qi] = v.w * 0.125f;
    }

    float o[4][4];
    float m[4], l[4];
#pragma unroll
    for (int i = 0; i < 4; i++) {
        m[i] = -3.0e38f; l[i] = 0.f;
#pragma unroll
        for (int j = 0; j < 4; j++) o[i][j] = 0.f;
    }

    for (int kt = 0; kt <= qt; kt++) {
        const int k0 = kt * 64;
        __syncthreads();
#pragma unroll
        for (int r = 0; r < 4; r++) {
            int fi = tid + r * 256;
            int ki = fi >> 4;
            int d4 = (fi & 15) * 4;
            float4 kv = *(const float4*)(kb + (size_t)(k0 + ki) * C3 + d4);
            Ks[(d4 + 0) * 68 + ki] = kv.x; Ks[(d4 + 1) * 68 + ki] = kv.y;
            Ks[(d4 + 2) * 68 + ki] = kv.z; Ks[(d4 + 3) * 68 + ki] = kv.w;
            float4 vv = *(const float4*)(vb + (size_t)(k0 + ki) * C3 + d4);
            *(float4*)&Vs[ki * 68 + d4] = vv;
        }
        __syncthreads();

        float s[4][4];
#pragma unroll
        for (int i = 0; i < 4; i++)
#pragma unroll
            for (int j = 0; j < 4; j++) s[i][j] = 0.f;
#pragma unroll 8
        for (int d = 0; d < 64; d++) {
            float4 qa = *(const float4*)&Qs[d * 68 + ty * 4];
            float4 ka = *(const float4*)&Ks[d * 68 + tx * 4];
            float aq[4] = {qa.x, qa.y, qa.z, qa.w};
            float ak[4] = {ka.x, ka.y, ka.z, ka.w};
#pragma unroll
            for (int i = 0; i < 4; i++)
#pragma unroll
                for (int j = 0; j < 4; j++)
                    s[i][j] += aq[i] * ak[j];
        }

        if (kt == qt) {
#pragma unroll
            for (int i = 0; i < 4; i++)
#pragma unroll
                for (int j = 0; j < 4; j++)
                    if (tx * 4 + j > ty * 4 + i) s[i][j] = -3.0e38f;
        }

#pragma unroll
        for (int i = 0; i < 4; i++) {
            float mx = fmaxf(fmaxf(s[i][0], s[i][1]), fmaxf(s[i][2], s[i][3]));
#pragma unroll
            for (int off = 8; off; off >>= 1)
                mx = fmaxf(mx, __shfl_xor_sync(0xffffffffu, mx, off));
            float mn = fmaxf(m[i], mx);
            float corr = __expf(m[i] - mn);
            float rs = 0.f;
#pragma unroll
            for (int j = 0; j < 4; j++) {
                float p = __expf(s[i][j] - mn);
                s[i][j] = p;
                rs += p;
            }
#pragma unroll
            for (int off = 8; off; off >>= 1)
                rs += __shfl_xor_sync(0xffffffffu, rs, off);
            l[i] = l[i] * corr + rs;
            m[i] = mn;
#pragma unroll
            for (int j = 0; j < 4; j++) o[i][j] *= corr;
#pragma unroll
            for (int j = 0; j < 4; j++)
                Ps[(ty * 4 + i) * 64 + tx * 4 + j] = s[i][j];
        }
        __syncthreads();

#pragma unroll 4
        for (int kj = 0; kj < 64; kj++) {
            float4 v = *(const float4*)&Vs[kj * 68 + tx * 4];
#pragma unroll
            for (int i = 0; i < 4; i++) {
                float p = Ps[(ty * 4 + i) * 64 + kj];
                o[i][0] += p * v.x; o[i][1] += p * v.y;
                o[i][2] += p * v.z; o[i][3] += p * v.w;
            }
        }
    }

#pragma unroll
    for (int i = 0; i < 4; i++) {
        float inv = 1.0f / l[i];
        float4 st = make_float4(o[i][0] * inv, o[i][1] * inv,
                                o[i][2] * inv, o[i][3] * inv);
        *(float4*)(y + (size_t)(b * T_SEQ + q0 + ty * 4 + i) * C_DIM + h * HD + tx * 4) = st;
    }
}

// ---------------------------------------------------------------------------
extern "C" void kernel_launch(void* const* d_in, const int* in_sizes, int n_in,
                              void* d_out, int out_size) {
    const float* x      = (const float*)d_in[0];
    const float* w_qkv  = (const float*)d_in[1];
    const float* w_proj = (const float*)d_in[2];
    float* out = (float*)d_out;

    float *qkv, *y;
    cudaGetSymbolAddress((void**)&qkv, g_qkv);
    cudaGetSymbolAddress((void**)&y, g_y);

    const int flash_smem = (3 * 64 * 68 + 64 * 64) * 4;  // 68608
    cudaFuncSetAttribute(flash_kernel, cudaFuncAttributeMaxDynamicSharedMemorySize, flash_smem);

    // 1) QKV projection: (4096,3072) = x @ w_qkv^T  (tensor cores)
    gemm_mma<<<dim3(C3 / 128, M_ROWS / 128), 256>>>(x, w_qkv, qkv, M_ROWS, C3, C_DIM);

    // 2) RoPE in place
    rope_kernel<<<(M_ROWS * 1024) / 256, 256>>>(qkv);

    // 3) Causal flash attention (fp32)
    flash_kernel<<<dim3(T_SEQ / 64, 2 * NH), 256, flash_smem>>>(qkv, y);

    // 4) Output projection: (4096,1024) = y @ w_proj^T  (tensor cores)
    gemm_mma<<<dim3(C_DIM / 128, M_ROWS / 128), 256>>>(y, w_proj, out, M_ROWS, C_DIM, C_DIM);
}

// round 8
// speedup vs baseline: 2.5127x; 1.6717x over previous
#include <cuda_runtime.h>
#include <cuda_bf16.h>
#include <math.h>
#include <cstdint>

#define T_SEQ 2048
#define C_DIM 1024
#define C3    3072
#define NH    16
#define HD    64
#define M_ROWS 4096   // B*T

// Scratch (static device arrays — allocation-guard safe)
__device__ float g_qkv[(size_t)M_ROWS * C3];   // (B*T, 3C)
__device__ float g_y[(size_t)M_ROWS * C_DIM];  // attention output

__device__ __forceinline__ uint32_t smem_u32(const void* p) {
    uint32_t a;
    asm("{ .reg .u64 t; cvta.to.shared.u64 t, %1; cvt.u32.u64 %0, t; }"
        : "=r"(a) : "l"(p));
    return a;
}

__device__ __forceinline__ void mma_bf16(float* c, const uint32_t* a, const uint32_t* b) {
    asm volatile(
        "mma.sync.aligned.m16n8k16.row.col.f32.bf16.bf16.f32 "
        "{%0,%1,%2,%3}, {%4,%5,%6,%7}, {%8,%9}, {%0,%1,%2,%3};"
        : "+f"(c[0]), "+f"(c[1]), "+f"(c[2]), "+f"(c[3])
        : "r"(a[0]), "r"(a[1]), "r"(a[2]), "r"(a[3]), "r"(b[0]), "r"(b[1]));
}
__device__ __forceinline__ void ldmx4(uint32_t* r, uint32_t addr) {
    asm volatile("ldmatrix.sync.aligned.m8n8.x4.shared.b16 {%0,%1,%2,%3}, [%4];"
        : "=r"(r[0]), "=r"(r[1]), "=r"(r[2]), "=r"(r[3]) : "r"(addr));
}
__device__ __forceinline__ void ldmx4t(uint32_t* r, uint32_t addr) {
    asm volatile("ldmatrix.sync.aligned.m8n8.x4.trans.shared.b16 {%0,%1,%2,%3}, [%4];"
        : "=r"(r[0]), "=r"(r[1]), "=r"(r[2]), "=r"(r[3]) : "r"(addr));
}
__device__ __forceinline__ void ldmx2(uint32_t* r, uint32_t addr) {
    asm volatile("ldmatrix.sync.aligned.m8n8.x2.shared.b16 {%0,%1}, [%2];"
        : "=r"(r[0]), "=r"(r[1]) : "r"(addr));
}
__device__ __forceinline__ float fast_exp2(float x) {
    float r;
    asm("ex2.approx.ftz.f32 %0, %1;" : "=f"(r) : "f"(x));
    return r;
}
__device__ __forceinline__ uint32_t pack_hi(float a, float b) {
    __nv_bfloat162 h = __floats2bfloat162_rn(a, b);
    return *(uint32_t*)&h;
}
__device__ __forceinline__ uint32_t pack_lo(float a, float b, uint32_t hi) {
    __nv_bfloat162 h = *(__nv_bfloat162*)&hi;
    float2 f = __bfloat1622float2(h);
    __nv_bfloat162 l = __floats2bfloat162_rn(a - f.x, b - f.y);
    return *(uint32_t*)&l;
}

// ---------------------------------------------------------------------------
// Tensor-core GEMM (NT): C = A @ B^T, fp32 in/out, bf16 3-product split.
// ---------------------------------------------------------------------------
#define ASTRIDE 40

__global__ __launch_bounds__(256, 2) void gemm_mma(const float* __restrict__ A,
                                                   const float* __restrict__ B,
                                                   float* __restrict__ C,
                                                   int M, int N, int K) {
    __shared__ __align__(16) __nv_bfloat16 sA[2][128 * ASTRIDE];
    __shared__ __align__(16) __nv_bfloat16 sB[2][128 * ASTRIDE];

    const int tid = threadIdx.x;
    const int wid = tid >> 5, lane = tid & 31;
    const int wm = wid >> 2, wn = wid & 3;
    const int m0 = blockIdx.y * 128;
    const int n0 = blockIdx.x * 128;

    float acc[4][4][4];
#pragma unroll
    for (int i = 0; i < 4; i++)
#pragma unroll
        for (int j = 0; j < 4; j++)
#pragma unroll
            for (int r = 0; r < 4; r++) acc[i][j][r] = 0.f;

    const uint32_t saddr0 = smem_u32(&sA[0][0]);
    const uint32_t sbddr0 = smem_u32(&sB[0][0]);
    const uint32_t a_base = saddr0 + ((wm * 64 + (lane & 15)) * ASTRIDE) * 2 + (lane >> 4) * 16;
    const uint32_t b_base = sbddr0 + ((wn * 32 + (lane & 7)) * ASTRIDE) * 2 + ((lane >> 3) & 1) * 16;
    const uint32_t PLANE = 128 * ASTRIDE * 2;

    const float* pA = A + (size_t)m0 * K;
    const float* pB = B + (size_t)n0 * K;

    for (int kt = 0; kt < K; kt += 32) {
        __syncthreads();
#pragma unroll
        for (int r = 0; r < 4; r++) {
            int idx = tid + 256 * r;
            int row = idx >> 3;
            int c4 = (idx & 7) << 2;
            float4 v = *(const float4*)(pA + (size_t)row * K + kt + c4);
            __nv_bfloat162 h0 = __floats2bfloat162_rn(v.x, v.y);
            __nv_bfloat162 h1 = __floats2bfloat162_rn(v.z, v.w);
            float2 f0 = __bfloat1622float2(h0);
            float2 f1 = __bfloat1622float2(h1);
            __nv_bfloat162 l0 = __floats2bfloat162_rn(v.x - f0.x, v.y - f0.y);
            __nv_bfloat162 l1 = __floats2bfloat162_rn(v.z - f1.x, v.w - f1.y);
            *(__nv_bfloat162*)&sA[0][row * ASTRIDE + c4] = h0;
            *(__nv_bfloat162*)&sA[0][row * ASTRIDE + c4 + 2] = h1;
            *(__nv_bfloat162*)&sA[1][row * ASTRIDE + c4] = l0;
            *(__nv_bfloat162*)&sA[1][row * ASTRIDE + c4 + 2] = l1;
            v = *(const float4*)(pB + (size_t)row * K + kt + c4);
            h0 = __floats2bfloat162_rn(v.x, v.y);
            h1 = __floats2bfloat162_rn(v.z, v.w);
            f0 = __bfloat1622float2(h0);
            f1 = __bfloat1622float2(h1);
            l0 = __floats2bfloat162_rn(v.x - f0.x, v.y - f0.y);
            l1 = __floats2bfloat162_rn(v.z - f1.x, v.w - f1.y);
            *(__nv_bfloat162*)&sB[0][row * ASTRIDE + c4] = h0;
            *(__nv_bfloat162*)&sB[0][row * ASTRIDE + c4 + 2] = h1;
            *(__nv_bfloat162*)&sB[1][row * ASTRIDE + c4] = l0;
            *(__nv_bfloat162*)&sB[1][row * ASTRIDE + c4 + 2] = l1;
        }
        __syncthreads();

#pragma unroll
        for (int ks = 0; ks < 2; ks++) {
            uint32_t bhi[4][2], blo[4][2];
#pragma unroll
            for (int nt = 0; nt < 4; nt++) {
                uint32_t ba = b_base + nt * (8 * ASTRIDE * 2) + ks * 32;
                ldmx2(bhi[nt], ba);
                ldmx2(blo[nt], ba + PLANE);
            }
#pragma unroll
            for (int mt = 0; mt < 4; mt++) {
                uint32_t ahi[4], alo[4];
                uint32_t aa = a_base + mt * (16 * ASTRIDE * 2) + ks * 32;
                ldmx4(ahi, aa);
                ldmx4(alo, aa + PLANE);
#pragma unroll
                for (int nt = 0; nt < 4; nt++) {
                    mma_bf16(acc[mt][nt], ahi, bhi[nt]);
                    mma_bf16(acc[mt][nt], alo, bhi[nt]);
                    mma_bf16(acc[mt][nt], ahi, blo[nt]);
                }
            }
        }
    }

#pragma unroll
    for (int mt = 0; mt < 4; mt++) {
#pragma unroll
        for (int nt = 0; nt < 4; nt++) {
            int gm = m0 + wm * 64 + mt * 16 + (lane >> 2);
            int gn = n0 + wn * 32 + nt * 8 + (lane & 3) * 2;
            *(float2*)&C[(size_t)gm * N + gn] = make_float2(acc[mt][nt][0], acc[mt][nt][1]);
            *(float2*)&C[(size_t)(gm + 8) * N + gn] = make_float2(acc[mt][nt][2], acc[mt][nt][3]);
        }
    }
}

// ---------------------------------------------------------------------------
// RoPE: in place on q, k planes of g_qkv.
// ---------------------------------------------------------------------------
__global__ __launch_bounds__(256) void rope_kernel(float* __restrict__ qkv) {
    int idx = blockIdx.x * blockDim.x + threadIdx.x;
    int row = idx >> 10;
    int p   = idx & 1023;
    int col = p * 2;
    int t   = row & (T_SEQ - 1);
    int dd  = col & (HD - 1);
    float theta = (float)exp((double)dd * -0.14391156831212787);
    float ang = (float)t * theta;
    float sn, cs;
    sincosf(ang, &sn, &cs);
    float2* ptr = (float2*)(qkv + (size_t)row * C3 + col);
    float2 v = *ptr;
    *ptr = make_float2(v.x * cs - v.y * sn, v.y * cs + v.x * sn);
}

// ---------------------------------------------------------------------------
// Flash attention on tensor cores. Q tile 128x64 (8 warps x 16 rows),
// K/V tiles 64x64, bf16 hi/lo split (3 MMAs per product), online softmax
// in fragments, causal tile skipping.
// ---------------------------------------------------------------------------
#define FSTRIDE 72               // bf16 elems per smem row (64 + 8 pad)
#define QPLANE  (128 * FSTRIDE * 2)   // bytes
#define KPLANE  (64 * FSTRIDE * 2)    // bytes

__global__ __launch_bounds__(256, 1) void flash_mma(const float* __restrict__ qkv,
                                                    float* __restrict__ y) {
    __shared__ __align__(16) char smem[2 * QPLANE];   // 36864 B

    const int tid = threadIdx.x;
    const int wid = tid >> 5, lane = tid & 31;
    const int qi = gridDim.x - 1 - blockIdx.x;   // heavy CTAs first
    const int q0 = qi * 128;
    const int b = blockIdx.y >> 4, h = blockIdx.y & 15;

    const float* qb = qkv + (size_t)b * T_SEQ * C3 + h * HD;
    const float* kb = qb + C_DIM;
    const float* vb = qb + 2 * C_DIM;

    __nv_bfloat16* Qh = (__nv_bfloat16*)smem;
    __nv_bfloat16* Kh = (__nv_bfloat16*)smem;
    __nv_bfloat16* Kl = Kh + 64 * FSTRIDE;
    __nv_bfloat16* Vh = Kl + 64 * FSTRIDE;
    __nv_bfloat16* Vl = Vh + 64 * FSTRIDE;

    const float qscale = 0.125f * 1.4426950408889634f;  // 1/sqrt(D) * log2(e)

    // ---- stage Q (scaled), split hi/lo ----
#pragma unroll
    for (int r = 0; r < 8; r++) {
        int idx = tid + r * 256;
        int row = idx >> 4, c4 = (idx & 15) << 2;
        float4 v = *(const float4*)(qb + (size_t)(q0 + row) * C3 + c4);
        v.x *= qscale; v.y *= qscale; v.z *= qscale; v.w *= qscale;
        uint32_t h0 = pack_hi(v.x, v.y);
        uint32_t h1 = pack_hi(v.z, v.w);
        uint32_t l0 = pack_lo(v.x, v.y, h0);
        uint32_t l1 = pack_lo(v.z, v.w, h1);
        *(uint32_t*)&Qh[row * FSTRIDE + c4] = h0;
        *(uint32_t*)&Qh[row * FSTRIDE + c4 + 2] = h1;
        *(uint32_t*)&Qh[128 * FSTRIDE + row * FSTRIDE + c4] = l0;
        *(uint32_t*)&Qh[128 * FSTRIDE + row * FSTRIDE + c4 + 2] = l1;
    }
    __syncthreads();

    // ---- Q fragments to registers ----
    uint32_t qfh[4][4], qfl[4][4];
    {
        uint32_t qaddr = smem_u32(Qh) + ((wid * 16 + (lane & 15)) * FSTRIDE) * 2 + (lane >> 4) * 16;
#pragma unroll
        for (int kc = 0; kc < 4; kc++) {
            ldmx4(qfh[kc], qaddr + kc * 32);
            ldmx4(qfl[kc], qaddr + kc * 32 + QPLANE);
        }
    }
    __syncthreads();  // Q smem now reusable for K/V

    float o[8][4];
#pragma unroll
    for (int j = 0; j < 8; j++)
#pragma unroll
        for (int r = 0; r < 4; r++) o[j][r] = 0.f;
    float m0 = -1e30f, m1 = -1e30f, l0 = 0.f, l1 = 0.f;

    const int q0w = q0 + wid * 16;  // warp's first q row
    const int nkt = 2 * qi + 2;

    // per-thread ldmatrix bases (within-tile byte offsets)
    const uint32_t kaddr0 = smem_u32(Kh) + ((lane & 7) * FSTRIDE) * 2 +
                            ((lane >> 3) & 1) * 16 + (lane >> 4) * 32;
    const uint32_t vaddr0 = smem_u32(Vh) + (((lane & 7) + ((lane >> 3) & 3) * 8) * FSTRIDE) * 2;

    for (int kt = 0; kt < nkt; kt++) {
        const int k0 = kt * 64;
        __syncthreads();
        // ---- load K,V tiles, split hi/lo ----
#pragma unroll
        for (int r = 0; r < 4; r++) {
            int idx = tid + r * 256;
            int row = idx >> 4, c4 = (idx & 15) << 2;
            float4 v = *(const float4*)(kb + (size_t)(k0 + row) * C3 + c4);
            uint32_t h0 = pack_hi(v.x, v.y);
            uint32_t h1 = pack_hi(v.z, v.w);
            *(uint32_t*)&Kh[row * FSTRIDE + c4] = h0;
            *(uint32_t*)&Kh[row * FSTRIDE + c4 + 2] = h1;
            *(uint32_t*)&Kl[row * FSTRIDE + c4] = pack_lo(v.x, v.y, h0);
            *(uint32_t*)&Kl[row * FSTRIDE + c4 + 2] = pack_lo(v.z, v.w, h1);
            v = *(const float4*)(vb + (size_t)(k0 + row) * C3 + c4);
            h0 = pack_hi(v.x, v.y);
            h1 = pack_hi(v.z, v.w);
            *(uint32_t*)&Vh[row * FSTRIDE + c4] = h0;
            *(uint32_t*)&Vh[row * FSTRIDE + c4 + 2] = h1;
            *(uint32_t*)&Vl[row * FSTRIDE + c4] = pack_lo(v.x, v.y, h0);
            *(uint32_t*)&Vl[row * FSTRIDE + c4 + 2] = pack_lo(v.z, v.w, h1);
        }
        __syncthreads();

        if (k0 > q0w + 15) continue;   // tile fully above diagonal for this warp

        // ---- S = Q K^T ----
        float s[8][4];
#pragma unroll
        for (int j = 0; j < 8; j++)
#pragma unroll
            for (int r = 0; r < 4; r++) s[j][r] = 0.f;

#pragma unroll
        for (int kp = 0; kp < 2; kp++) {
#pragma unroll
            for (int j = 0; j < 8; j++) {
                uint32_t kfh[4], kfl[4];
                uint32_t ka = kaddr0 + (j * 8 * FSTRIDE) * 2 + kp * 64;
                ldmx4(kfh, ka);
                ldmx4(kfl, ka + KPLANE);
                mma_bf16(s[j], qfh[2 * kp], kfh);
                mma_bf16(s[j], qfl[2 * kp], kfh);
                mma_bf16(s[j], qfh[2 * kp], kfl);
                mma_bf16(s[j], qfh[2 * kp + 1], kfh + 2);
                mma_bf16(s[j], qfl[2 * kp + 1], kfh + 2);
                mma_bf16(s[j], qfh[2 * kp + 1], kfl + 2);
            }
        }

        // ---- causal mask (diagonal tiles) ----
        if (k0 + 63 > q0w) {
            int gq0 = q0w + (lane >> 2);
            int cb = k0 + 2 * (lane & 3);
#pragma unroll
            for (int j = 0; j < 8; j++) {
                int c = cb + 8 * j;
                if (c > gq0)     s[j][0] = -1e30f;
                if (c + 1 > gq0) s[j][1] = -1e30f;
                if (c > gq0 + 8)     s[j][2] = -1e30f;
                if (c + 1 > gq0 + 8) s[j][3] = -1e30f;
            }
        }

        // ---- online softmax in fragments ----
        float mx0 = -1e30f, mx1 = -1e30f;
#pragma unroll
        for (int j = 0; j < 8; j++) {
            mx0 = fmaxf(mx0, fmaxf(s[j][0], s[j][1]));
            mx1 = fmaxf(mx1, fmaxf(s[j][2], s[j][3]));
        }
        mx0 = fmaxf(mx0, __shfl_xor_sync(0xffffffffu, mx0, 1));
        mx0 = fmaxf(mx0, __shfl_xor_sync(0xffffffffu, mx0, 2));
        mx1 = fmaxf(mx1, __shfl_xor_sync(0xffffffffu, mx1, 1));
        mx1 = fmaxf(mx1, __shfl_xor_sync(0xffffffffu, mx1, 2));
        float mn0 = fmaxf(m0, mx0), mn1 = fmaxf(m1, mx1);
        float c0 = fast_exp2(m0 - mn0), c1 = fast_exp2(m1 - mn1);
        m0 = mn0; m1 = mn1;

        uint32_t ph[4][4], pl[4][4];
        float rs0 = 0.f, rs1 = 0.f;
#pragma unroll
        for (int j = 0; j < 8; j++) {
            float p0 = fast_exp2(s[j][0] - mn0);
            float p1 = fast_exp2(s[j][1] - mn0);
            float p2 = fast_exp2(s[j][2] - mn1);
            float p3 = fast_exp2(s[j][3] - mn1);
            rs0 += p0 + p1; rs1 += p2 + p3;
            int kc = j >> 1, a0 = (j & 1) * 2;
            uint32_t h01 = pack_hi(p0, p1);
            uint32_t h23 = pack_hi(p2, p3);
            ph[kc][a0] = h01; ph[kc][a0 + 1] = h23;
            pl[kc][a0] = pack_lo(p0, p1, h01);
            pl[kc][a0 + 1] = pack_lo(p2, p3, h23);
        }
        rs0 += __shfl_xor_sync(0xffffffffu, rs0, 1);
        rs0 += __shfl_xor_sync(0xffffffffu, rs0, 2);
        rs1 += __shfl_xor_sync(0xffffffffu, rs1, 1);
        rs1 += __shfl_xor_sync(0xffffffffu, rs1, 2);
        l0 = l0 * c0 + rs0;
        l1 = l1 * c1 + rs1;
#pragma unroll
        for (int j = 0; j < 8; j++) {
            o[j][0] *= c0; o[j][1] *= c0;
            o[j][2] *= c1; o[j][3] *= c1;
        }

        // ---- O += P @ V ----
#pragma unroll
        for (int kp = 0; kp < 2; kp++) {
#pragma unroll
            for (int j = 0; j < 8; j++) {
                uint32_t vfh[4], vfl[4];
                uint32_t va = vaddr0 + (kp * 32 * FSTRIDE) * 2 + j * 16;
                ldmx4t(vfh, va);
                ldmx4t(vfl, va + KPLANE);
                mma_bf16(o[j], ph[2 * kp], vfh);
                mma_bf16(o[j], pl[2 * kp], vfh);
                mma_bf16(o[j], ph[2 * kp], vfl);
                mma_bf16(o[j], ph[2 * kp + 1], vfh + 2);
                mma_bf16(o[j], pl[2 * kp + 1], vfh + 2);
                mma_bf16(o[j], ph[2 * kp + 1], vfl + 2);
            }
        }
    }

    // ---- epilogue ----
    float inv0 = 1.0f / l0, inv1 = 1.0f / l1;
    int gq0 = q0w + (lane >> 2);
    float* y0 = y + (size_t)(b * T_SEQ + gq0) * C_DIM + h * HD + 2 * (lane & 3);
    float* y1 = y0 + 8 * C_DIM;
#pragma unroll
    for (int j = 0; j < 8; j++) {
        *(float2*)(y0 + 8 * j) = make_float2(o[j][0] * inv0, o[j][1] * inv0);
        *(float2*)(y1 + 8 * j) = make_float2(o[j][2] * inv1, o[j][3] * inv1);
    }
}

// ---------------------------------------------------------------------------
extern "C" void kernel_launch(void* const* d_in, const int* in_sizes, int n_in,
                              void* d_out, int out_size) {
    const float* x      = (const float*)d_in[0];
    const float* w_qkv  = (const float*)d_in[1];
    const float* w_proj = (const float*)d_in[2];
    float* out = (float*)d_out;

    float *qkv, *y;
    cudaGetSymbolAddress((void**)&qkv, g_qkv);
    cudaGetSymbolAddress((void**)&y, g_y);

    // 1) QKV projection
    gemm_mma<<<dim3(C3 / 128, M_ROWS / 128), 256>>>(x, w_qkv, qkv, M_ROWS, C3, C_DIM);

    // 2) RoPE in place
    rope_kernel<<<(M_ROWS * 1024) / 256, 256>>>(qkv);

    // 3) Causal flash attention (tensor cores)
    flash_mma<<<dim3(T_SEQ / 128, 2 * NH), 256>>>(qkv, y);

    // 4) Output projection
    gemm_mma<<<dim3(C_DIM / 128, M_ROWS / 128), 256>>>(y, w_proj, out, M_ROWS, C_DIM, C_DIM);
}

// round 9
// speedup vs baseline: 2.5534x; 1.0162x over previous
#include <cuda_runtime.h>
#include <cuda_bf16.h>
#include <math.h>
#include <cstdint>

#define T_SEQ 2048
#define C_DIM 1024
#define C3    3072
#define NH    16
#define HD    64
#define M_ROWS 4096   // B*T

// ---------------------------------------------------------------------------
// Scratch (static device arrays — allocation-guard safe)
// ---------------------------------------------------------------------------
__device__ float g_qkv[(size_t)M_ROWS * C3];            // fp32 between gemm1 and rope
__device__ __nv_bfloat16 g_xh[(size_t)M_ROWS * C_DIM], g_xl[(size_t)M_ROWS * C_DIM];
__device__ __nv_bfloat16 g_wqh[(size_t)C3 * C_DIM],    g_wql[(size_t)C3 * C_DIM];
__device__ __nv_bfloat16 g_wph[(size_t)C_DIM * C_DIM], g_wpl[(size_t)C_DIM * C_DIM];
// per-head [ (b*NH+h)*T + t ][64] planes
__device__ __nv_bfloat16 g_qh[(size_t)2 * NH * T_SEQ * HD], g_ql[(size_t)2 * NH * T_SEQ * HD];
__device__ __nv_bfloat16 g_kh[(size_t)2 * NH * T_SEQ * HD], g_kl[(size_t)2 * NH * T_SEQ * HD];
__device__ __nv_bfloat16 g_vh[(size_t)2 * NH * T_SEQ * HD], g_vl[(size_t)2 * NH * T_SEQ * HD];
__device__ __nv_bfloat16 g_yh[(size_t)M_ROWS * C_DIM], g_yl[(size_t)M_ROWS * C_DIM];

// ---------------------------------------------------------------------------
// helpers
// ---------------------------------------------------------------------------
__device__ __forceinline__ uint32_t smem_u32(const void* p) {
    uint32_t a;
    asm("{ .reg .u64 t; cvta.to.shared.u64 t, %1; cvt.u32.u64 %0, t; }"
        : "=r"(a) : "l"(p));
    return a;
}
__device__ __forceinline__ void mma_bf16(float* c, const uint32_t* a, const uint32_t* b) {
    asm volatile(
        "mma.sync.aligned.m16n8k16.row.col.f32.bf16.bf16.f32 "
        "{%0,%1,%2,%3}, {%4,%5,%6,%7}, {%8,%9}, {%0,%1,%2,%3};"
        : "+f"(c[0]), "+f"(c[1]), "+f"(c[2]), "+f"(c[3])
        : "r"(a[0]), "r"(a[1]), "r"(a[2]), "r"(a[3]), "r"(b[0]), "r"(b[1]));
}
__device__ __forceinline__ void ldmx4(uint32_t* r, uint32_t addr) {
    asm volatile("ldmatrix.sync.aligned.m8n8.x4.shared.b16 {%0,%1,%2,%3}, [%4];"
        : "=r"(r[0]), "=r"(r[1]), "=r"(r[2]), "=r"(r[3]) : "r"(addr));
}
__device__ __forceinline__ void ldmx4t(uint32_t* r, uint32_t addr) {
    asm volatile("ldmatrix.sync.aligned.m8n8.x4.trans.shared.b16 {%0,%1,%2,%3}, [%4];"
        : "=r"(r[0]), "=r"(r[1]), "=r"(r[2]), "=r"(r[3]) : "r"(addr));
}
__device__ __forceinline__ float fast_exp2(float x) {
    float r;
    asm("ex2.approx.ftz.f32 %0, %1;" : "=f"(r) : "f"(x));
    return r;
}
__device__ __forceinline__ uint32_t pack_hi(float a, float b) {
    __nv_bfloat162 h = __floats2bfloat162_rn(a, b);
    return *(uint32_t*)&h;
}
__device__ __forceinline__ uint32_t pack_lo(float a, float b, uint32_t hi) {
    __nv_bfloat162 h = *(__nv_bfloat162*)&hi;
    float2 f = __bfloat1622float2(h);
    __nv_bfloat162 l = __floats2bfloat162_rn(a - f.x, b - f.y);
    return *(uint32_t*)&l;
}
__device__ __forceinline__ void cp16(uint32_t dst, const void* src) {
    asm volatile("cp.async.cg.shared.global [%0], [%1], 16;" :: "r"(dst), "l"(src));
}
__device__ __forceinline__ void cp_commit() {
    asm volatile("cp.async.commit_group;" ::: "memory");
}
template <int N>
__device__ __forceinline__ void cp_wait() {
    asm volatile("cp.async.wait_group %0;" :: "n"(N) : "memory");
}

// ---------------------------------------------------------------------------
// fp32 -> (bf16 hi, bf16 lo) split pre-pass
// ---------------------------------------------------------------------------
__global__ __launch_bounds__(256) void split_bf16(const float* __restrict__ in,
                                                  __nv_bfloat16* __restrict__ hi,
                                                  __nv_bfloat16* __restrict__ lo,
                                                  int n4) {
    int i = blockIdx.x * blockDim.x + threadIdx.x;
    if (i >= n4) return;
    float4 v = ((const float4*)in)[i];
    uint32_t h0 = pack_hi(v.x, v.y);
    uint32_t h1 = pack_hi(v.z, v.w);
    ((uint2*)hi)[i] = make_uint2(h0, h1);
    ((uint2*)lo)[i] = make_uint2(pack_lo(v.x, v.y, h0), pack_lo(v.z, v.w, h1));
}

// ---------------------------------------------------------------------------
// RoPE + split: qkv fp32 -> per-head bf16 hi/lo planes (q scaled by 1/8*log2e)
// ---------------------------------------------------------------------------
__global__ __launch_bounds__(256) void rope_split(
    const float* __restrict__ qkv,
    __nv_bfloat16* __restrict__ qh, __nv_bfloat16* __restrict__ ql,
    __nv_bfloat16* __restrict__ kh, __nv_bfloat16* __restrict__ kl,
    __nv_bfloat16* __restrict__ vh, __nv_bfloat16* __restrict__ vl) {
    int idx = blockIdx.x * 256 + threadIdx.x;   // 1,048,576 total
    int g = idx & 15;
    int rowh = idx >> 4;           // (b*16+h)*2048 + t
    int t = rowh & (T_SEQ - 1);
    int bh = rowh >> 11;
    int b = bh >> 4, h = bh & 15;
    const float* base = qkv + ((size_t)(b * T_SEQ + t)) * C3 + h * HD + g * 4;
    float4 q = *(const float4*)base;
    float4 k = *(const float4*)(base + C_DIM);
    float4 v = *(const float4*)(base + 2 * C_DIM);
    int d0 = g * 4;
    float th0 = (float)exp((double)d0 * -0.14391156831212787);
    float th1 = (float)exp((double)(d0 + 2) * -0.14391156831212787);
    float s0, c0, s1, c1;
    sincosf((float)t * th0, &s0, &c0);
    sincosf((float)t * th1, &s1, &c1);
    const float qs = 0.125f * 1.4426950408889634f;
    float qx = (q.x * c0 - q.y * s0) * qs, qy = (q.y * c0 + q.x * s0) * qs;
    float qz = (q.z * c1 - q.w * s1) * qs, qw = (q.w * c1 + q.z * s1) * qs;
    float kx = k.x * c0 - k.y * s0, ky = k.y * c0 + k.x * s0;
    float kz = k.z * c1 - k.w * s1, kw = k.w * c1 + k.z * s1;
    size_t oi = (size_t)rowh * 16 + g;   // uint2 index (8B = 4 bf16)
    uint32_t h0 = pack_hi(qx, qy), h1 = pack_hi(qz, qw);
    ((uint2*)qh)[oi] = make_uint2(h0, h1);
    ((uint2*)ql)[oi] = make_uint2(pack_lo(qx, qy, h0), pack_lo(qz, qw, h1));
    h0 = pack_hi(kx, ky); h1 = pack_hi(kz, kw);
    ((uint2*)kh)[oi] = make_uint2(h0, h1);
    ((uint2*)kl)[oi] = make_uint2(pack_lo(kx, ky, h0), pack_lo(kz, kw, h1));
    h0 = pack_hi(v.x, v.y); h1 = pack_hi(v.z, v.w);
    ((uint2*)vh)[oi] = make_uint2(h0, h1);
    ((uint2*)vl)[oi] = make_uint2(pack_lo(v.x, v.y, h0), pack_lo(v.z, v.w, h1));
}

// ---------------------------------------------------------------------------
// Pipelined tensor-core GEMM (NT): C = A @ B^T, bf16 hi/lo in, fp32 out.
// Block 128x128, K-tile 32, 2-stage cp.async double buffer, 8 warps.
// Stage layout (bytes): Ah@0, Al@10240, Bh@20480, Bl@30720; rows 80B (32+8 bf16)
// ---------------------------------------------------------------------------
#define GSTG 40960

__global__ __launch_bounds__(256, 2) void gemm_bf16_pipe(
    const __nv_bfloat16* __restrict__ Ah, const __nv_bfloat16* __restrict__ Al,
    const __nv_bfloat16* __restrict__ Bh, const __nv_bfloat16* __restrict__ Bl,
    float* __restrict__ C, int M, int N, int K) {
    extern __shared__ char smem[];
    const uint32_t sb = smem_u32(smem);
    const int tid = threadIdx.x;
    const int wid = tid >> 5, lane = tid & 31;
    const int wm = wid >> 2, wn = wid & 3;
    const int m0 = blockIdx.y * 128, n0 = blockIdx.x * 128;

    float acc[4][4][4];
#pragma unroll
    for (int i = 0; i < 4; i++)
#pragma unroll
        for (int j = 0; j < 4; j++)
#pragma unroll
            for (int r = 0; r < 4; r++) acc[i][j][r] = 0.f;

    auto issue_tile = [&](int kt, int stg) {
        uint32_t base = sb + stg * GSTG;
#pragma unroll
        for (int r = 0; r < 8; r++) {
            const int plane = r >> 1;
            const int row = (r & 1) * 64 + (tid >> 2);
            const int ch = tid & 3;
            uint32_t dst = base + plane * 10240 + row * 80 + ch * 16;
            const __nv_bfloat16* src;
            if (plane == 0)      src = Ah + (size_t)(m0 + row) * K + kt + ch * 8;
            else if (plane == 1) src = Al + (size_t)(m0 + row) * K + kt + ch * 8;
            else if (plane == 2) src = Bh + (size_t)(n0 + row) * K + kt + ch * 8;
            else                 src = Bl + (size_t)(n0 + row) * K + kt + ch * 8;
            cp16(dst, src);
        }
        cp_commit();
    };

    issue_tile(0, 0);
    const int nk = K >> 5;

    const uint32_t a_off = (uint32_t)((wm * 64 + (lane & 15)) * 80 + (lane >> 4) * 16);
    const uint32_t b_off = (uint32_t)(20480 + (wn * 32 + (lane & 15)) * 80 + (lane >> 4) * 16);

    for (int kt = 0; kt < nk; kt++) {
        const int cur = kt & 1;
        if (kt + 1 < nk) { issue_tile((kt + 1) << 5, cur ^ 1); cp_wait<1>(); }
        else             { cp_wait<0>(); }
        __syncthreads();

        const uint32_t tb = sb + cur * GSTG;
#pragma unroll
        for (int ks = 0; ks < 2; ks++) {
            uint32_t b4h[2][4], b4l[2][4];
#pragma unroll
            for (int np = 0; np < 2; np++) {
                uint32_t ba = tb + b_off + np * (16 * 80) + ks * 32;
                ldmx4(b4h[np], ba);
                ldmx4(b4l[np], ba + 10240);
            }
#pragma unroll
            for (int mt = 0; mt < 4; mt++) {
                uint32_t ahi[4], alo[4];
                uint32_t aa = tb + a_off + mt * (16 * 80) + ks * 32;
                ldmx4(ahi, aa);
                ldmx4(alo, aa + 10240);
#pragma unroll
                for (int nt = 0; nt < 4; nt++) {
                    const int np = nt >> 1, sel = nt & 1;
                    uint32_t bh2[2] = { b4h[np][sel], b4h[np][sel + 2] };
                    uint32_t bl2[2] = { b4l[np][sel], b4l[np][sel + 2] };
                    mma_bf16(acc[mt][nt], ahi, bh2);
                    mma_bf16(acc[mt][nt], alo, bh2);
                    mma_bf16(acc[mt][nt], ahi, bl2);
                }
            }
        }
        __syncthreads();
    }

#pragma unroll
    for (int mt = 0; mt < 4; mt++) {
#pragma unroll
        for (int nt = 0; nt < 4; nt++) {
            int gm = m0 + wm * 64 + mt * 16 + (lane >> 2);
            int gn = n0 + wn * 32 + nt * 8 + (lane & 3) * 2;
            *(float2*)&C[(size_t)gm * N + gn] = make_float2(acc[mt][nt][0], acc[mt][nt][1]);
            *(float2*)&C[(size_t)(gm + 8) * N + gn] = make_float2(acc[mt][nt][2], acc[mt][nt][3]);
        }
    }
}

// ---------------------------------------------------------------------------
// Pipelined flash attention. Q 128x64/CTA (8 warps x 16 rows), K/V 64x64 tiles,
// 2-stage cp.async, bf16 hi/lo inputs pre-split, fragment softmax.
// Stage layout (bytes): Kh@0, Kl@9216, Vh@18432, Vl@27648; rows 144B (64+8 bf16)
// ---------------------------------------------------------------------------
#define FSTG 36864

__global__ __launch_bounds__(256) void flash_pipe(
    const __nv_bfloat16* __restrict__ qh, const __nv_bfloat16* __restrict__ ql,
    const __nv_bfloat16* __restrict__ kh, const __nv_bfloat16* __restrict__ kl,
    const __nv_bfloat16* __restrict__ vh, const __nv_bfloat16* __restrict__ vl,
    __nv_bfloat16* __restrict__ yh, __nv_bfloat16* __restrict__ yl) {
    extern __shared__ char smem[];
    const uint32_t sb = smem_u32(smem);
    const int tid = threadIdx.x;
    const int wid = tid >> 5, lane = tid & 31;
    const int qi = gridDim.x - 1 - blockIdx.x;   // heavy CTAs first
    const int q0 = qi * 128;
    const int bh = blockIdx.y;
    const size_t hT = (size_t)bh << 11;

    // ---- stage Q (hi@0, lo@18432), rows 144B ----
#pragma unroll
    for (int r = 0; r < 8; r++) {
        const int plane = r >> 2;
        const int c = (r & 3) * 256 + tid;
        const int row = c >> 3, ch = c & 7;
        uint32_t dst = sb + plane * 18432 + row * 144 + ch * 16;
        const __nv_bfloat16* src = (plane ? ql : qh) + (hT + q0 + row) * HD + ch * 8;
        cp16(dst, src);
    }
    cp_commit();
    cp_wait<0>();
    __syncthreads();

    uint32_t qfh[4][4], qfl[4][4];
    {
        uint32_t qaddr = sb + (wid * 16 + (lane & 15)) * 144 + (lane >> 4) * 16;
#pragma unroll
        for (int kc = 0; kc < 4; kc++) {
            ldmx4(qfh[kc], qaddr + kc * 32);
            ldmx4(qfl[kc], qaddr + kc * 32 + 18432);
        }
    }
    __syncthreads();   // Q smem area now reusable as K/V stage buffers

    auto issue_kv = [&](int k0, int stg) {
        uint32_t base = sb + stg * FSTG;
#pragma unroll
        for (int r = 0; r < 8; r++) {
            const int plane = r >> 1;
            const int c = (r & 1) * 256 + tid;
            const int row = c >> 3, ch = c & 7;
            uint32_t dst = base + plane * 9216 + row * 144 + ch * 16;
            const __nv_bfloat16* p = (plane == 0) ? kh : (plane == 1) ? kl
                                   : (plane == 2) ? vh : vl;
            cp16(dst, p + (hT + k0 + row) * HD + ch * 8);
        }
        cp_commit();
    };
    issue_kv(0, 0);

    float o[8][4];
#pragma unroll
    for (int j = 0; j < 8; j++)
#pragma unroll
        for (int r = 0; r < 4; r++) o[j][r] = 0.f;
    float m0v = -1e30f, m1v = -1e30f, l0v = 0.f, l1v = 0.f;

    const int q0w = q0 + wid * 16;
    const int nkt = 2 * qi + 2;

    for (int kt = 0; kt < nkt; kt++) {
        const int cur = kt & 1;
        if (kt + 1 < nkt) { issue_kv((kt + 1) * 64, cur ^ 1); cp_wait<1>(); }
        else              { cp_wait<0>(); }
        __syncthreads();
        const int k0 = kt * 64;

        if (k0 <= q0w + 15) {
            const uint32_t bb = sb + cur * FSTG;
            const uint32_t kaddr0 = bb + (lane & 7) * 144 + ((lane >> 3) & 1) * 16 + (lane >> 4) * 32;
            const uint32_t vaddr0 = bb + 18432 + ((lane & 7) + ((lane >> 3) & 3) * 8) * 144;

            // ---- S = Q K^T ----
            float s[8][4];
#pragma unroll
            for (int j = 0; j < 8; j++)
#pragma unroll
                for (int r = 0; r < 4; r++) s[j][r] = 0.f;
#pragma unroll
            for (int kp = 0; kp < 2; kp++) {
#pragma unroll
                for (int j = 0; j < 8; j++) {
                    uint32_t kfh[4], kfl[4];
                    uint32_t ka = kaddr0 + j * (8 * 144) + kp * 64;
                    ldmx4(kfh, ka);
                    ldmx4(kfl, ka + 9216);
                    mma_bf16(s[j], qfh[2 * kp], kfh);
                    mma_bf16(s[j], qfl[2 * kp], kfh);
                    mma_bf16(s[j], qfh[2 * kp], kfl);
                    mma_bf16(s[j], qfh[2 * kp + 1], kfh + 2);
                    mma_bf16(s[j], qfl[2 * kp + 1], kfh + 2);
                    mma_bf16(s[j], qfh[2 * kp + 1], kfl + 2);
                }
            }

            // ---- causal mask (diagonal tiles) ----
            if (k0 + 63 > q0w) {
                int gq0 = q0w + (lane >> 2);
                int cb = k0 + 2 * (lane & 3);
#pragma unroll
                for (int j = 0; j < 8; j++) {
                    int c = cb + 8 * j;
                    if (c > gq0)         s[j][0] = -1e30f;
                    if (c + 1 > gq0)     s[j][1] = -1e30f;
                    if (c > gq0 + 8)     s[j][2] = -1e30f;
                    if (c + 1 > gq0 + 8) s[j][3] = -1e30f;
                }
            }

            // ---- online softmax ----
            float mx0 = -1e30f, mx1 = -1e30f;
#pragma unroll
            for (int j = 0; j < 8; j++) {
                mx0 = fmaxf(mx0, fmaxf(s[j][0], s[j][1]));
                mx1 = fmaxf(mx1, fmaxf(s[j][2], s[j][3]));
            }
            mx0 = fmaxf(mx0, __shfl_xor_sync(0xffffffffu, mx0, 1));
            mx0 = fmaxf(mx0, __shfl_xor_sync(0xffffffffu, mx0, 2));
            mx1 = fmaxf(mx1, __shfl_xor_sync(0xffffffffu, mx1, 1));
            mx1 = fmaxf(mx1, __shfl_xor_sync(0xffffffffu, mx1, 2));
            float mn0 = fmaxf(m0v, mx0), mn1 = fmaxf(m1v, mx1);
            float c0 = fast_exp2(m0v - mn0), c1 = fast_exp2(m1v - mn1);
            m0v = mn0; m1v = mn1;

            uint32_t ph[4][4], pl[4][4];
            float rs0 = 0.f, rs1 = 0.f;
#pragma unroll
            for (int j = 0; j < 8; j++) {
                float p0 = fast_exp2(s[j][0] - mn0);
                float p1 = fast_exp2(s[j][1] - mn0);
                float p2 = fast_exp2(s[j][2] - mn1);
                float p3 = fast_exp2(s[j][3] - mn1);
                rs0 += p0 + p1; rs1 += p2 + p3;
                int kc = j >> 1, a0 = (j & 1) * 2;
                uint32_t h01 = pack_hi(p0, p1);
                uint32_t h23 = pack_hi(p2, p3);
                ph[kc][a0] = h01; ph[kc][a0 + 1] = h23;
                pl[kc][a0] = pack_lo(p0, p1, h01);
                pl[kc][a0 + 1] = pack_lo(p2, p3, h23);
            }
            rs0 += __shfl_xor_sync(0xffffffffu, rs0, 1);
            rs0 += __shfl_xor_sync(0xffffffffu, rs0, 2);
            rs1 += __shfl_xor_sync(0xffffffffu, rs1, 1);
            rs1 += __shfl_xor_sync(0xffffffffu, rs1, 2);
            l0v = l0v * c0 + rs0;
            l1v = l1v * c1 + rs1;
#pragma unroll
            for (int j = 0; j < 8; j++) {
                o[j][0] *= c0; o[j][1] *= c0;
                o[j][2] *= c1; o[j][3] *= c1;
            }

            // ---- O += P @ V ----
#pragma unroll
            for (int kp = 0; kp < 2; kp++) {
#pragma unroll
                for (int j = 0; j < 8; j++) {
                    uint32_t vfh[4], vfl[4];
                    uint32_t va = vaddr0 + kp * (32 * 144) + j * 16;
                    ldmx4t(vfh, va);
                    ldmx4t(vfl, va + 9216);
                    mma_bf16(o[j], ph[2 * kp], vfh);
                    mma_bf16(o[j], pl[2 * kp], vfh);
                    mma_bf16(o[j], ph[2 * kp], vfl);
                    mma_bf16(o[j], ph[2 * kp + 1], vfh + 2);
                    mma_bf16(o[j], pl[2 * kp + 1], vfh + 2);
                    mma_bf16(o[j], ph[2 * kp + 1], vfl + 2);
                }
            }
        }
        __syncthreads();
    }

    // ---- epilogue: write y as bf16 hi/lo for the proj GEMM ----
    float inv0 = 1.0f / l0v, inv1 = 1.0f / l1v;
    int gq = q0w + (lane >> 2);
    size_t base0 = ((size_t)((bh >> 4) * T_SEQ + gq)) * C_DIM + (bh & 15) * HD + 2 * (lane & 3);
    size_t base1 = base0 + 8 * C_DIM;
#pragma unroll
    for (int j = 0; j < 8; j++) {
        float f0 = o[j][0] * inv0, f1 = o[j][1] * inv0;
        uint32_t h = pack_hi(f0, f1);
        *(uint32_t*)&yh[base0 + 8 * j] = h;
        *(uint32_t*)&yl[base0 + 8 * j] = pack_lo(f0, f1, h);
        float f2 = o[j][2] * inv1, f3 = o[j][3] * inv1;
        h = pack_hi(f2, f3);
        *(uint32_t*)&yh[base1 + 8 * j] = h;
        *(uint32_t*)&yl[base1 + 8 * j] = pack_lo(f2, f3, h);
    }
}

// ---------------------------------------------------------------------------
extern "C" void kernel_launch(void* const* d_in, const int* in_sizes, int n_in,
                              void* d_out, int out_size) {
    const float* x      = (const float*)d_in[0];
    const float* w_qkv  = (const float*)d_in[1];
    const float* w_proj = (const float*)d_in[2];
    float* out = (float*)d_out;

    float* qkv;
    __nv_bfloat16 *xh, *xl, *wqh, *wql, *wph, *wpl;
    __nv_bfloat16 *qh, *ql, *kh, *kl, *vh, *vl, *yh, *yl;
    cudaGetSymbolAddress((void**)&qkv, g_qkv);
    cudaGetSymbolAddress((void**)&xh, g_xh);   cudaGetSymbolAddress((void**)&xl, g_xl);
    cudaGetSymbolAddress((void**)&wqh, g_wqh); cudaGetSymbolAddress((void**)&wql, g_wql);
    cudaGetSymbolAddress((void**)&wph, g_wph); cudaGetSymbolAddress((void**)&wpl, g_wpl);
    cudaGetSymbolAddress((void**)&qh, g_qh);   cudaGetSymbolAddress((void**)&ql, g_ql);
    cudaGetSymbolAddress((void**)&kh, g_kh);   cudaGetSymbolAddress((void**)&kl, g_kl);
    cudaGetSymbolAddress((void**)&vh, g_vh);   cudaGetSymbolAddress((void**)&vl, g_vl);
    cudaGetSymbolAddress((void**)&yh, g_yh);   cudaGetSymbolAddress((void**)&yl, g_yl);

    cudaFuncSetAttribute(gemm_bf16_pipe, cudaFuncAttributeMaxDynamicSharedMemorySize, 2 * GSTG);
    cudaFuncSetAttribute(flash_pipe, cudaFuncAttributeMaxDynamicSharedMemorySize, 2 * FSTG);

    // 0) split inputs to bf16 hi/lo
    split_bf16<<<M_ROWS * C_DIM / 4 / 256, 256>>>(x, xh, xl, M_ROWS * C_DIM / 4);
    split_bf16<<<C3 * C_DIM / 4 / 256, 256>>>(w_qkv, wqh, wql, C3 * C_DIM / 4);
    split_bf16<<<C_DIM * C_DIM / 4 / 256, 256>>>(w_proj, wph, wpl, C_DIM * C_DIM / 4);

    // 1) QKV projection (fp32 out)
    gemm_bf16_pipe<<<dim3(C3 / 128, M_ROWS / 128), 256, 2 * GSTG>>>(
        xh, xl, wqh, wql, qkv, M_ROWS, C3, C_DIM);

    // 2) RoPE + per-head bf16 split
    rope_split<<<M_ROWS * NH * 16 / 256, 256>>>(qkv, qh, ql, kh, kl, vh, vl);

    // 3) Flash attention -> y bf16 hi/lo
    flash_pipe<<<dim3(T_SEQ / 128, 2 * NH), 256, 2 * FSTG>>>(
        qh, ql, kh, kl, vh, vl, yh, yl);

    // 4) Output projection
    gemm_bf16_pipe<<<dim3(C_DIM / 128, M_ROWS / 128), 256, 2 * GSTG>>>(
        yh, yl, wph, wpl, out, M_ROWS, C_DIM, C_DIM);
}

// round 10
// speedup vs baseline: 2.6070x; 1.0210x over previous
#include <cuda_runtime.h>
#include <cuda_bf16.h>
#include <math.h>
#include <cstdint>

#define T_SEQ 2048
#define C_DIM 1024
#define C3    3072
#define NH    16
#define HD    64
#define M_ROWS 4096   // B*T

// ---------------------------------------------------------------------------
// Scratch (static device arrays — allocation-guard safe)
// ---------------------------------------------------------------------------
__device__ float g_qkv[(size_t)M_ROWS * C3];
__device__ __nv_bfloat16 g_xh[(size_t)M_ROWS * C_DIM], g_xl[(size_t)M_ROWS * C_DIM];
__device__ __nv_bfloat16 g_wqh[(size_t)C3 * C_DIM],    g_wql[(size_t)C3 * C_DIM];
__device__ __nv_bfloat16 g_wph[(size_t)C_DIM * C_DIM], g_wpl[(size_t)C_DIM * C_DIM];
__device__ __nv_bfloat16 g_qh[(size_t)2 * NH * T_SEQ * HD], g_ql[(size_t)2 * NH * T_SEQ * HD];
__device__ __nv_bfloat16 g_kh[(size_t)2 * NH * T_SEQ * HD], g_kl[(size_t)2 * NH * T_SEQ * HD];
__device__ __nv_bfloat16 g_vh[(size_t)2 * NH * T_SEQ * HD], g_vl[(size_t)2 * NH * T_SEQ * HD];
__device__ __nv_bfloat16 g_yh[(size_t)M_ROWS * C_DIM], g_yl[(size_t)M_ROWS * C_DIM];

// ---------------------------------------------------------------------------
// helpers
// ---------------------------------------------------------------------------
__device__ __forceinline__ uint32_t smem_u32(const void* p) {
    uint32_t a;
    asm("{ .reg .u64 t; cvta.to.shared.u64 t, %1; cvt.u32.u64 %0, t; }"
        : "=r"(a) : "l"(p));
    return a;
}
__device__ __forceinline__ void mma_bf16(float* c, const uint32_t* a, const uint32_t* b) {
    asm volatile(
        "mma.sync.aligned.m16n8k16.row.col.f32.bf16.bf16.f32 "
        "{%0,%1,%2,%3}, {%4,%5,%6,%7}, {%8,%9}, {%0,%1,%2,%3};"
        : "+f"(c[0]), "+f"(c[1]), "+f"(c[2]), "+f"(c[3])
        : "r"(a[0]), "r"(a[1]), "r"(a[2]), "r"(a[3]), "r"(b[0]), "r"(b[1]));
}
__device__ __forceinline__ void mma2(float* c, const uint32_t* a, uint32_t b0, uint32_t b1) {
    asm volatile(
        "mma.sync.aligned.m16n8k16.row.col.f32.bf16.bf16.f32 "
        "{%0,%1,%2,%3}, {%4,%5,%6,%7}, {%8,%9}, {%0,%1,%2,%3};"
        : "+f"(c[0]), "+f"(c[1]), "+f"(c[2]), "+f"(c[3])
        : "r"(a[0]), "r"(a[1]), "r"(a[2]), "r"(a[3]), "r"(b0), "r"(b1));
}
__device__ __forceinline__ void ldmx4(uint32_t* r, uint32_t addr) {
    asm volatile("ldmatrix.sync.aligned.m8n8.x4.shared.b16 {%0,%1,%2,%3}, [%4];"
        : "=r"(r[0]), "=r"(r[1]), "=r"(r[2]), "=r"(r[3]) : "r"(addr));
}
__device__ __forceinline__ void ldmx4t(uint32_t* r, uint32_t addr) {
    asm volatile("ldmatrix.sync.aligned.m8n8.x4.trans.shared.b16 {%0,%1,%2,%3}, [%4];"
        : "=r"(r[0]), "=r"(r[1]), "=r"(r[2]), "=r"(r[3]) : "r"(addr));
}
__device__ __forceinline__ float fast_exp2(float x) {
    float r;
    asm("ex2.approx.ftz.f32 %0, %1;" : "=f"(r) : "f"(x));
    return r;
}
__device__ __forceinline__ uint32_t pack_hi(float a, float b) {
    __nv_bfloat162 h = __floats2bfloat162_rn(a, b);
    return *(uint32_t*)&h;
}
__device__ __forceinline__ uint32_t pack_lo(float a, float b, uint32_t hi) {
    __nv_bfloat162 h = *(__nv_bfloat162*)&hi;
    float2 f = __bfloat1622float2(h);
    __nv_bfloat162 l = __floats2bfloat162_rn(a - f.x, b - f.y);
    return *(uint32_t*)&l;
}
__device__ __forceinline__ void cp16(uint32_t dst, const void* src) {
    asm volatile("cp.async.cg.shared.global [%0], [%1], 16;" :: "r"(dst), "l"(src));
}
__device__ __forceinline__ void cp_commit() {
    asm volatile("cp.async.commit_group;" ::: "memory");
}
template <int N>
__device__ __forceinline__ void cp_wait() {
    asm volatile("cp.async.wait_group %0;" :: "n"(N) : "memory");
}

// ---------------------------------------------------------------------------
// fp32 -> (bf16 hi, bf16 lo) split pre-pass
// ---------------------------------------------------------------------------
__global__ __launch_bounds__(256) void split_bf16(const float* __restrict__ in,
                                                  __nv_bfloat16* __restrict__ hi,
                                                  __nv_bfloat16* __restrict__ lo,
                                                  int n4) {
    int i = blockIdx.x * blockDim.x + threadIdx.x;
    if (i >= n4) return;
    float4 v = ((const float4*)in)[i];
    uint32_t h0 = pack_hi(v.x, v.y);
    uint32_t h1 = pack_hi(v.z, v.w);
    ((uint2*)hi)[i] = make_uint2(h0, h1);
    ((uint2*)lo)[i] = make_uint2(pack_lo(v.x, v.y, h0), pack_lo(v.z, v.w, h1));
}

// ---------------------------------------------------------------------------
// RoPE + split: qkv fp32 -> per-head bf16 hi/lo planes (q scaled by 1/8*log2e)
// ---------------------------------------------------------------------------
__global__ __launch_bounds__(256) void rope_split(
    const float* __restrict__ qkv,
    __nv_bfloat16* __restrict__ qh, __nv_bfloat16* __restrict__ ql,
    __nv_bfloat16* __restrict__ kh, __nv_bfloat16* __restrict__ kl,
    __nv_bfloat16* __restrict__ vh, __nv_bfloat16* __restrict__ vl) {
    int idx = blockIdx.x * 256 + threadIdx.x;
    int g = idx & 15;
    int rowh = idx >> 4;
    int t = rowh & (T_SEQ - 1);
    int bh = rowh >> 11;
    int b = bh >> 4, h = bh & 15;
    const float* base = qkv + ((size_t)(b * T_SEQ + t)) * C3 + h * HD + g * 4;
    float4 q = *(const float4*)base;
    float4 k = *(const float4*)(base + C_DIM);
    float4 v = *(const float4*)(base + 2 * C_DIM);
    int d0 = g * 4;
    float th0 = (float)exp((double)d0 * -0.14391156831212787);
    float th1 = (float)exp((double)(d0 + 2) * -0.14391156831212787);
    float s0, c0, s1, c1;
    sincosf((float)t * th0, &s0, &c0);
    sincosf((float)t * th1, &s1, &c1);
    const float qs = 0.125f * 1.4426950408889634f;
    float qx = (q.x * c0 - q.y * s0) * qs, qy = (q.y * c0 + q.x * s0) * qs;
    float qz = (q.z * c1 - q.w * s1) * qs, qw = (q.w * c1 + q.z * s1) * qs;
    float kx = k.x * c0 - k.y * s0, ky = k.y * c0 + k.x * s0;
    float kz = k.z * c1 - k.w * s1, kw = k.w * c1 + k.z * s1;
    size_t oi = (size_t)rowh * 16 + g;
    uint32_t h0 = pack_hi(qx, qy), h1 = pack_hi(qz, qw);
    ((uint2*)qh)[oi] = make_uint2(h0, h1);
    ((uint2*)ql)[oi] = make_uint2(pack_lo(qx, qy, h0), pack_lo(qz, qw, h1));
    h0 = pack_hi(kx, ky); h1 = pack_hi(kz, kw);
    ((uint2*)kh)[oi] = make_uint2(h0, h1);
    ((uint2*)kl)[oi] = make_uint2(pack_lo(kx, ky, h0), pack_lo(kz, kw, h1));
    h0 = pack_hi(v.x, v.y); h1 = pack_hi(v.z, v.w);
    ((uint2*)vh)[oi] = make_uint2(h0, h1);
    ((uint2*)vl)[oi] = make_uint2(pack_lo(v.x, v.y, h0), pack_lo(v.z, v.w, h1));
}

// ---------------------------------------------------------------------------
// Tensor-core GEMM (NT): C = A @ B^T.  Block 128x64, 4 warps (2x2), warp 64x32,
// K-tile 32, 2-stage cp.async, single sync/tile, term-grouped MMAs.
// Row layout: [hi 64B | lo 64B | pad 16B] = 144B.  A rows 0-127, B rows 128-191.
// ---------------------------------------------------------------------------
#define GSTAGE 27648   // 192 rows * 144B

__global__ __launch_bounds__(128, 4) void gemm_bf16_v2(
    const __nv_bfloat16* __restrict__ Ah, const __nv_bfloat16* __restrict__ Al,
    const __nv_bfloat16* __restrict__ Bh, const __nv_bfloat16* __restrict__ Bl,
    float* __restrict__ C, int M, int N, int K) {
    extern __shared__ char smem[];
    const uint32_t sb = smem_u32(smem);
    const int tid = threadIdx.x;
    const int wid = tid >> 5, lane = tid & 31;
    const int wm = wid >> 1, wn = wid & 1;
    const int m0 = blockIdx.y * 128, n0 = blockIdx.x * 64;

    float acc[4][4][4];
#pragma unroll
    for (int i = 0; i < 4; i++)
#pragma unroll
        for (int j = 0; j < 4; j++)
#pragma unroll
            for (int r = 0; r < 4; r++) acc[i][j][r] = 0.f;

    auto issue_tile = [&](int kt, int stg) {
        uint32_t base = sb + stg * GSTAGE;
#pragma unroll
        for (int i = 0; i < 12; i++) {
            int c = i * 128 + tid;
            int row = c >> 3, ch = c & 7;
            uint32_t dst = base + row * 144 + ch * 16;
            const __nv_bfloat16* src;
            if (row < 128)
                src = (ch < 4 ? Ah : Al) + (size_t)(m0 + row) * K + kt + (ch & 3) * 8;
            else
                src = (ch < 4 ? Bh : Bl) + (size_t)(n0 + row - 128) * K + kt + (ch & 3) * 8;
            cp16(dst, src);
        }
        cp_commit();
    };

    issue_tile(0, 0);
    const int nk = K >> 5;

    const uint32_t a_off = (uint32_t)((wm * 64 + (lane & 15)) * 144 + (lane >> 4) * 16);
    const uint32_t b_off = (uint32_t)(128 * 144 + (wn * 32 + (lane & 15)) * 144 + (lane >> 4) * 16);

    for (int kt = 0; kt < nk; kt++) {
        cp_wait<0>();
        __syncthreads();
        if (kt + 1 < nk) issue_tile((kt + 1) << 5, (kt + 1) & 1);

        const uint32_t tb = sb + (kt & 1) * GSTAGE;
#pragma unroll
        for (int ks = 0; ks < 2; ks++) {
            uint32_t b4h[2][4], b4l[2][4];
#pragma unroll
            for (int np = 0; np < 2; np++) {
                uint32_t ba = tb + b_off + np * (16 * 144) + ks * 32;
                ldmx4(b4h[np], ba);
                ldmx4(b4l[np], ba + 64);
            }
#pragma unroll
            for (int mt = 0; mt < 4; mt++) {
                uint32_t ahi[4], alo[4];
                uint32_t aa = tb + a_off + mt * (16 * 144) + ks * 32;
                ldmx4(ahi, aa);
                ldmx4(alo, aa + 64);
                // term-grouped: 4 independent chains per group
#pragma unroll
                for (int nt = 0; nt < 4; nt++)
                    mma2(acc[mt][nt], ahi, b4h[nt >> 1][nt & 1], b4h[nt >> 1][(nt & 1) + 2]);
#pragma unroll
                for (int nt = 0; nt < 4; nt++)
                    mma2(acc[mt][nt], alo, b4h[nt >> 1][nt & 1], b4h[nt >> 1][(nt & 1) + 2]);
#pragma unroll
                for (int nt = 0; nt < 4; nt++)
                    mma2(acc[mt][nt], ahi, b4l[nt >> 1][nt & 1], b4l[nt >> 1][(nt & 1) + 2]);
            }
        }
    }

#pragma unroll
    for (int mt = 0; mt < 4; mt++) {
#pragma unroll
        for (int nt = 0; nt < 4; nt++) {
            int gm = m0 + wm * 64 + mt * 16 + (lane >> 2);
            int gn = n0 + wn * 32 + nt * 8 + (lane & 3) * 2;
            *(float2*)&C[(size_t)gm * N + gn] = make_float2(acc[mt][nt][0], acc[mt][nt][1]);
            *(float2*)&C[(size_t)(gm + 8) * N + gn] = make_float2(acc[mt][nt][2], acc[mt][nt][3]);
        }
    }
}

// ---------------------------------------------------------------------------
// Flash attention. Q 128x64/CTA (8 warps x 16 rows), K/V 64x64 tiles.
// Rows: [hi 128B | lo 128B | pad 16B] = 272B.  K rows 0-63, V rows 64-127.
// 2-stage cp.async, single sync/tile, pair-interleaved MMA chains.
// ---------------------------------------------------------------------------
#define FSTAGE 34816   // 128 rows * 272B
#define VOFF   (64 * 272)

__global__ __launch_bounds__(256) void flash_v2(
    const __nv_bfloat16* __restrict__ qh, const __nv_bfloat16* __restrict__ ql,
    const __nv_bfloat16* __restrict__ kh, const __nv_bfloat16* __restrict__ kl,
    const __nv_bfloat16* __restrict__ vh, const __nv_bfloat16* __restrict__ vl,
    __nv_bfloat16* __restrict__ yh, __nv_bfloat16* __restrict__ yl) {
    extern __shared__ char smem[];
    const uint32_t sb = smem_u32(smem);
    const int tid = threadIdx.x;
    const int wid = tid >> 5, lane = tid & 31;
    const int qi = gridDim.x - 1 - blockIdx.x;
    const int q0 = qi * 128;
    const int bh = blockIdx.y;
    const size_t hT = (size_t)bh << 11;

    // ---- stage Q into stage0 (rows 272B: hi|lo) ----
#pragma unroll
    for (int i = 0; i < 8; i++) {
        int c = i * 256 + tid;
        int row = c >> 4, ch = c & 15;
        uint32_t dst = sb + row * 272 + ch * 16;
        const __nv_bfloat16* src = (ch < 8 ? qh : ql) + (hT + q0 + row) * HD + (ch & 7) * 8;
        cp16(dst, src);
    }
    cp_commit();
    cp_wait<0>();
    __syncthreads();

    uint32_t qfh[4][4], qfl[4][4];
    {
        uint32_t qaddr = sb + (wid * 16 + (lane & 15)) * 272 + (lane >> 4) * 16;
#pragma unroll
        for (int kc = 0; kc < 4; kc++) {
            ldmx4(qfh[kc], qaddr + kc * 32);
            ldmx4(qfl[kc], qaddr + kc * 32 + 128);
        }
    }
    __syncthreads();

    auto issue_kv = [&](int k0, int stg) {
        uint32_t base = sb + stg * FSTAGE;
#pragma unroll
        for (int i = 0; i < 8; i++) {
            int c = i * 256 + tid;
            int row = c >> 4, ch = c & 15;
            uint32_t dst = base + row * 272 + ch * 16;
            const __nv_bfloat16* p;
            if (row < 64) p = (ch < 8 ? kh : kl) + (hT + k0 + row) * HD + (ch & 7) * 8;
            else          p = (ch < 8 ? vh : vl) + (hT + k0 + row - 64) * HD + (ch & 7) * 8;
            cp16(dst, p);
        }
        cp_commit();
    };
    issue_kv(0, 0);

    float o[8][4];
#pragma unroll
    for (int j = 0; j < 8; j++)
#pragma unroll
        for (int r = 0; r < 4; r++) o[j][r] = 0.f;
    float m0v = -1e30f, m1v = -1e30f, l0v = 0.f, l1v = 0.f;

    const int q0w = q0 + wid * 16;
    const int nkt = 2 * qi + 2;

    for (int kt = 0; kt < nkt; kt++) {
        cp_wait<0>();
        __syncthreads();
        if (kt + 1 < nkt) issue_kv((kt + 1) * 64, (kt + 1) & 1);
        const int k0 = kt * 64;

        if (k0 <= q0w + 15) {
            const uint32_t bb = sb + (kt & 1) * FSTAGE;
            const uint32_t kaddr0 = bb + (lane & 7) * 272 + ((lane >> 3) & 1) * 16 + (lane >> 4) * 32;
            const uint32_t vaddr0 = bb + VOFF + ((lane & 7) + ((lane >> 3) & 3) * 8) * 272;

            // ---- S = Q K^T (pair-interleaved chains) ----
            float s[8][4];
#pragma unroll
            for (int j = 0; j < 8; j++)
#pragma unroll
                for (int r = 0; r < 4; r++) s[j][r] = 0.f;
#pragma unroll
            for (int kp = 0; kp < 2; kp++) {
#pragma unroll
                for (int jp = 0; jp < 4; jp++) {
                    const int j0 = 2 * jp, j1 = 2 * jp + 1;
                    uint32_t kf0h[4], kf0l[4], kf1h[4], kf1l[4];
                    uint32_t ka0 = kaddr0 + j0 * (8 * 272) + kp * 64;
                    uint32_t ka1 = kaddr0 + j1 * (8 * 272) + kp * 64;
                    ldmx4(kf0h, ka0); ldmx4(kf0l, ka0 + 128);
                    ldmx4(kf1h, ka1); ldmx4(kf1l, ka1 + 128);
                    mma_bf16(s[j0], qfh[2 * kp], kf0h);     mma_bf16(s[j1], qfh[2 * kp], kf1h);
                    mma_bf16(s[j0], qfl[2 * kp], kf0h);     mma_bf16(s[j1], qfl[2 * kp], kf1h);
                    mma_bf16(s[j0], qfh[2 * kp], kf0l);     mma_bf16(s[j1], qfh[2 * kp], kf1l);
                    mma_bf16(s[j0], qfh[2 * kp + 1], kf0h + 2); mma_bf16(s[j1], qfh[2 * kp + 1], kf1h + 2);
                    mma_bf16(s[j0], qfl[2 * kp + 1], kf0h + 2); mma_bf16(s[j1], qfl[2 * kp + 1], kf1h + 2);
                    mma_bf16(s[j0], qfh[2 * kp + 1], kf0l + 2); mma_bf16(s[j1], qfh[2 * kp + 1], kf1l + 2);
                }
            }

            // ---- causal mask (diagonal tiles) ----
            if (k0 + 63 > q0w) {
                int gq0 = q0w + (lane >> 2);
                int cb = k0 + 2 * (lane & 3);
#pragma unroll
                for (int j = 0; j < 8; j++) {
                    int c = cb + 8 * j;
                    if (c > gq0)         s[j][0] = -1e30f;
                    if (c + 1 > gq0)     s[j][1] = -1e30f;
                    if (c > gq0 + 8)     s[j][2] = -1e30f;
                    if (c + 1 > gq0 + 8) s[j][3] = -1e30f;
                }
            }

            // ---- online softmax ----
            float mx0 = -1e30f, mx1 = -1e30f;
#pragma unroll
            for (int j = 0; j < 8; j++) {
                mx0 = fmaxf(mx0, fmaxf(s[j][0], s[j][1]));
                mx1 = fmaxf(mx1, fmaxf(s[j][2], s[j][3]));
            }
            mx0 = fmaxf(mx0, __shfl_xor_sync(0xffffffffu, mx0, 1));
            mx0 = fmaxf(mx0, __shfl_xor_sync(0xffffffffu, mx0, 2));
            mx1 = fmaxf(mx1, __shfl_xor_sync(0xffffffffu, mx1, 1));
            mx1 = fmaxf(mx1, __shfl_xor_sync(0xffffffffu, mx1, 2));
            float mn0 = fmaxf(m0v, mx0), mn1 = fmaxf(m1v, mx1);
            float c0 = fast_exp2(m0v - mn0), c1 = fast_exp2(m1v - mn1);
            m0v = mn0; m1v = mn1;

            uint32_t ph[4][4], pl[4][4];
            float rs0 = 0.f, rs1 = 0.f;
#pragma unroll
            for (int j = 0; j < 8; j++) {
                float p0 = fast_exp2(s[j][0] - mn0);
                float p1 = fast_exp2(s[j][1] - mn0);
                float p2 = fast_exp2(s[j][2] - mn1);
                float p3 = fast_exp2(s[j][3] - mn1);
                rs0 += p0 + p1; rs1 += p2 + p3;
                int kc = j >> 1, a0 = (j & 1) * 2;
                uint32_t h01 = pack_hi(p0, p1);
                uint32_t h23 = pack_hi(p2, p3);
                ph[kc][a0] = h01; ph[kc][a0 + 1] = h23;
                pl[kc][a0] = pack_lo(p0, p1, h01);
                pl[kc][a0 + 1] = pack_lo(p2, p3, h23);
            }
            rs0 += __shfl_xor_sync(0xffffffffu, rs0, 1);
            rs0 += __shfl_xor_sync(0xffffffffu, rs0, 2);
            rs1 += __shfl_xor_sync(0xffffffffu, rs1, 1);
            rs1 += __shfl_xor_sync(0xffffffffu, rs1, 2);
            l0v = l0v * c0 + rs0;
            l1v = l1v * c1 + rs1;
#pragma unroll
            for (int j = 0; j < 8; j++) {
                o[j][0] *= c0; o[j][1] *= c0;
                o[j][2] *= c1; o[j][3] *= c1;
            }

            // ---- O += P @ V (pair-interleaved chains) ----
#pragma unroll
            for (int kp = 0; kp < 2; kp++) {
#pragma unroll
                for (int jp = 0; jp < 4; jp++) {
                    const int j0 = 2 * jp, j1 = 2 * jp + 1;
                    uint32_t vf0h[4], vf0l[4], vf1h[4], vf1l[4];
                    uint32_t va0 = vaddr0 + kp * (32 * 272) + j0 * 16;
                    uint32_t va1 = vaddr0 + kp * (32 * 272) + j1 * 16;
                    ldmx4t(vf0h, va0); ldmx4t(vf0l, va0 + 128);
                    ldmx4t(vf1h, va1); ldmx4t(vf1l, va1 + 128);
                    mma_bf16(o[j0], ph[2 * kp], vf0h);     mma_bf16(o[j1], ph[2 * kp], vf1h);
                    mma_bf16(o[j0], pl[2 * kp], vf0h);     mma_bf16(o[j1], pl[2 * kp], vf1h);
                    mma_bf16(o[j0], ph[2 * kp], vf0l);     mma_bf16(o[j1], ph[2 * kp], vf1l);
                    mma_bf16(o[j0], ph[2 * kp + 1], vf0h + 2); mma_bf16(o[j1], ph[2 * kp + 1], vf1h + 2);
                    mma_bf16(o[j0], pl[2 * kp + 1], vf0h + 2); mma_bf16(o[j1], pl[2 * kp + 1], vf1h + 2);
                    mma_bf16(o[j0], ph[2 * kp + 1], vf0l + 2); mma_bf16(o[j1], ph[2 * kp + 1], vf1l + 2);
                }
            }
        }
    }

    // ---- epilogue: write y as bf16 hi/lo ----
    float inv0 = 1.0f / l0v, inv1 = 1.0f / l1v;
    int gq = q0w + (lane >> 2);
    size_t base0 = ((size_t)((bh >> 4) * T_SEQ + gq)) * C_DIM + (bh & 15) * HD + 2 * (lane & 3);
    size_t base1 = base0 + 8 * C_DIM;
#pragma unroll
    for (int j = 0; j < 8; j++) {
        float f0 = o[j][0] * inv0, f1 = o[j][1] * inv0;
        uint32_t h = pack_hi(f0, f1);
        *(uint32_t*)&yh[base0 + 8 * j] = h;
        *(uint32_t*)&yl[base0 + 8 * j] = pack_lo(f0, f1, h);
        float f2 = o[j][2] * inv1, f3 = o[j][3] * inv1;
        h = pack_hi(f2, f3);
        *(uint32_t*)&yh[base1 + 8 * j] = h;
        *(uint32_t*)&yl[base1 + 8 * j] = pack_lo(f2, f3, h);
    }
}

// ---------------------------------------------------------------------------
extern "C" void kernel_launch(void* const* d_in, const int* in_sizes, int n_in,
                              void* d_out, int out_size) {
    const float* x      = (const float*)d_in[0];
    const float* w_qkv  = (const float*)d_in[1];
    const float* w_proj = (const float*)d_in[2];
    float* out = (float*)d_out;

    float* qkv;
    __nv_bfloat16 *xh, *xl, *wqh, *wql, *wph, *wpl;
    __nv_bfloat16 *qh, *ql, *kh, *kl, *vh, *vl, *yh, *yl;
    cudaGetSymbolAddress((void**)&qkv, g_qkv);
    cudaGetSymbolAddress((void**)&xh, g_xh);   cudaGetSymbolAddress((void**)&xl, g_xl);
    cudaGetSymbolAddress((void**)&wqh, g_wqh); cudaGetSymbolAddress((void**)&wql, g_wql);
    cudaGetSymbolAddress((void**)&wph, g_wph); cudaGetSymbolAddress((void**)&wpl, g_wpl);
    cudaGetSymbolAddress((void**)&qh, g_qh);   cudaGetSymbolAddress((void**)&ql, g_ql);
    cudaGetSymbolAddress((void**)&kh, g_kh);   cudaGetSymbolAddress((void**)&kl, g_kl);
    cudaGetSymbolAddress((void**)&vh, g_vh);   cudaGetSymbolAddress((void**)&vl, g_vl);
    cudaGetSymbolAddress((void**)&yh, g_yh);   cudaGetSymbolAddress((void**)&yl, g_yl);

    cudaFuncSetAttribute(gemm_bf16_v2, cudaFuncAttributeMaxDynamicSharedMemorySize, 2 * GSTAGE);
    cudaFuncSetAttribute(flash_v2, cudaFuncAttributeMaxDynamicSharedMemorySize, 2 * FSTAGE);

    // 0) split inputs to bf16 hi/lo
    split_bf16<<<M_ROWS * C_DIM / 4 / 256, 256>>>(x, xh, xl, M_ROWS * C_DIM / 4);
    split_bf16<<<C3 * C_DIM / 4 / 256, 256>>>(w_qkv, wqh, wql, C3 * C_DIM / 4);
    split_bf16<<<C_DIM * C_DIM / 4 / 256, 256>>>(w_proj, wph, wpl, C_DIM * C_DIM / 4);

    // 1) QKV projection
    gemm_bf16_v2<<<dim3(C3 / 64, M_ROWS / 128), 128, 2 * GSTAGE>>>(
        xh, xl, wqh, wql, qkv, M_ROWS, C3, C_DIM);

    // 2) RoPE + per-head bf16 split
    rope_split<<<M_ROWS * NH * 16 / 256, 256>>>(qkv, qh, ql, kh, kl, vh, vl);

    // 3) Flash attention -> y bf16 hi/lo
    flash_v2<<<dim3(T_SEQ / 128, 2 * NH), 256, 2 * FSTAGE>>>(
        qh, ql, kh, kl, vh, vl, yh, yl);

    // 4) Output projection
    gemm_bf16_v2<<<dim3(C_DIM / 64, M_ROWS / 128), 128, 2 * GSTAGE>>>(
        yh, yl, wph, wpl, out, M_ROWS, C_DIM, C_DIM);
}